// round 1
// baseline (speedup 1.0000x reference)
#include <cuda_runtime.h>
#include <cstdint>
#include <cstddef>

// ---------------- problem constants ----------------
#define NN     50000
#define NE     800000
#define NG     32
#define HH     128
#define NDD    16
#define EDD    128
#define DD2D   64

#define NT_E   (NE/128)     // 6250 edge tiles of 128
#define NT_N   (NN/16)      // 3125 node tiles of 16

typedef unsigned long long ull;

// ---------------- scratch (device globals: no allocation allowed) ----------------
__device__ float g_cs[NG * HH];
__device__ float g_node[(size_t)NN * HH];
__device__ float g_eattr[(size_t)NE * HH];

// ---------------- helpers ----------------
__device__ __forceinline__ float gelu_f(float x) {
    return 0.5f * x * (1.0f + erff(x * 0.70710678118654752440f));
}

__device__ __forceinline__ ull pack2(float lo, float hi) {
    ull r; asm("mov.b64 %0, {%1, %2};" : "=l"(r) : "f"(lo), "f"(hi)); return r;
}
__device__ __forceinline__ void unpack2(ull v, float& lo, float& hi) {
    asm("mov.b64 {%0, %1}, %2;" : "=f"(lo), "=f"(hi) : "l"(v));
}
__device__ __forceinline__ ull fma2(ull a, ull b, ull c) {
    ull d; asm("fma.rn.f32x2 %0, %1, %2, %3;" : "=l"(d) : "l"(a), "l"(b), "l"(c)); return d;
}

__device__ __forceinline__ void cp16(void* sdst, const void* gsrc) {
    uint32_t sa = (uint32_t)__cvta_generic_to_shared(sdst);
    asm volatile("cp.async.ca.shared.global [%0], [%1], 16;" :: "r"(sa), "l"(gsrc));
}
#define CP_COMMIT() asm volatile("cp.async.commit_group;")
#define CP_WAIT0()  asm volatile("cp.async.wait_group 0;" ::: "memory")

// ======================================================================
// Kernel 0: cs[g] = gelu(concat(emb_chg[charge], emb_spin[spin]) @ W_cs + b_cs)
// ======================================================================
__global__ void cs_kernel(const int* __restrict__ charge, const int* __restrict__ spin,
                          const float* __restrict__ emb_chg, const float* __restrict__ emb_spin,
                          const float* __restrict__ W_cs, const float* __restrict__ b_cs) {
    __shared__ float xv[2 * HH];
    int g = blockIdx.x, j = threadIdx.x;
    int c = charge[g], s = spin[g];
    xv[j]      = emb_chg[c * HH + j];
    xv[HH + j] = emb_spin[s * HH + j];
    __syncthreads();
    float acc = b_cs[j];
    #pragma unroll 8
    for (int k = 0; k < 2 * HH; k++) acc += xv[k] * W_cs[k * HH + j];
    g_cs[g * HH + j] = gelu_f(acc);
}

// ======================================================================
// Kernel 1: node features (persistent; W_node resident in smem)
//   x = [emb_atom[a] | gelu(nde @ W_nd + b_nd)]  -> LN -> gelu(@W_node+b) + cs[batch]
// smem: W_node 256x128 (131072B) + sx 16x257 (16448B)
// ======================================================================
#define SX_STRIDE 257
#define SMEM_NODE ((32768 + 16 * SX_STRIDE) * 4)

__global__ void __launch_bounds__(256, 1)
node_kernel(const int* __restrict__ an, const float* __restrict__ nde,
            const int* __restrict__ nbatch,
            const float* __restrict__ emb_atom, const float* __restrict__ W_nd,
            const float* __restrict__ b_nd, const float* __restrict__ ln_g,
            const float* __restrict__ ln_b, const float* __restrict__ W_node,
            const float* __restrict__ b_node) {
    extern __shared__ float sm[];
    float* sW = sm;                  // [256][128]
    float* sx = sm + 32768;          // [16][257]
    __shared__ float smu[16], srs[16];
    int tid = threadIdx.x;

    for (int i = tid; i < 32768 / 4; i += 256)
        ((float4*)sW)[i] = ((const float4*)W_node)[i];

    for (int t0 = blockIdx.x; t0 < NT_N; t0 += gridDim.x) {
        __syncthreads();   // smem reuse fence (also orders sW load on iter 0)
        int n0 = t0 * 16;
        // build x[16][256]
        for (int idx = tid; idx < 16 * HH; idx += 256) {
            int n = idx >> 7, j = idx & 127;
            int node = n0 + n;
            float a = emb_atom[an[node] * HH + j];
            float accv = b_nd[j];
            const float* nrow = nde + node * NDD;
            #pragma unroll
            for (int k = 0; k < NDD; k++) accv += nrow[k] * W_nd[k * HH + j];
            sx[n * SX_STRIDE + j]      = a;
            sx[n * SX_STRIDE + HH + j] = gelu_f(accv);
        }
        __syncthreads();
        // layernorm stats: warp w handles nodes w, w+8
        int w = tid >> 5, lane = tid & 31;
        for (int n = w; n < 16; n += 8) {
            float s1 = 0.f, s2 = 0.f;
            for (int k = lane; k < 256; k += 32) {
                float v = sx[n * SX_STRIDE + k]; s1 += v; s2 += v * v;
            }
            #pragma unroll
            for (int o = 16; o > 0; o >>= 1) {
                s1 += __shfl_down_sync(0xffffffffu, s1, o);
                s2 += __shfl_down_sync(0xffffffffu, s2, o);
            }
            if (lane == 0) {
                float mu  = s1 * (1.f / 256.f);
                float var = s2 * (1.f / 256.f) - mu * mu;
                smu[n] = mu; srs[n] = rsqrtf(var + 1e-5f);
            }
        }
        __syncthreads();
        for (int idx = tid; idx < 16 * 256; idx += 256) {
            int n = idx >> 8, k = idx & 255;
            sx[n * SX_STRIDE + k] =
                (sx[n * SX_STRIDE + k] - smu[n]) * srs[n] * ln_g[k] + ln_b[k];
        }
        __syncthreads();
        // GEMM [16,256]@[256,128]: thread -> (node n, cols jb*8..jb*8+7)
        {
            int n = tid >> 4, jb = tid & 15;
            float acc[8];
            #pragma unroll
            for (int q = 0; q < 8; q++) acc[q] = b_node[jb * 8 + q];
            const float* xr = sx + n * SX_STRIDE;
            #pragma unroll 4
            for (int k = 0; k < 256; k++) {
                float a = xr[k];
                const float4 b0 = *(const float4*)&sW[k * HH + jb * 8];
                const float4 b1 = *(const float4*)&sW[k * HH + jb * 8 + 4];
                acc[0] += a * b0.x; acc[1] += a * b0.y; acc[2] += a * b0.z; acc[3] += a * b0.w;
                acc[4] += a * b1.x; acc[5] += a * b1.y; acc[6] += a * b1.z; acc[7] += a * b1.w;
            }
            int node = n0 + n;
            const float* csr = g_cs + nbatch[node] * HH;
            float4 o0, o1;
            o0.x = gelu_f(acc[0]) + csr[jb * 8 + 0];
            o0.y = gelu_f(acc[1]) + csr[jb * 8 + 1];
            o0.z = gelu_f(acc[2]) + csr[jb * 8 + 2];
            o0.w = gelu_f(acc[3]) + csr[jb * 8 + 3];
            o1.x = gelu_f(acc[4]) + csr[jb * 8 + 4];
            o1.y = gelu_f(acc[5]) + csr[jb * 8 + 5];
            o1.z = gelu_f(acc[6]) + csr[jb * 8 + 6];
            o1.w = gelu_f(acc[7]) + csr[jb * 8 + 7];
            *(float4*)&g_node[(size_t)node * HH + jb * 8]     = o0;
            *(float4*)&g_node[(size_t)node * HH + jb * 8 + 4] = o1;
        }
    }
}

// ======================================================================
// Edge GEMMs (persistent, weights in smem, cp.async double-buffered A,
// f32x2 packed FMA, 8 edges x 8 cols per thread)
//   MODE 0: eattr = gelu([edist|edir] @ W_edge + b)          K=192
//   MODE 1: out   = gelu([node[src]|eattr] @ W_ef + b)       K=256
// ======================================================================
#define SA_STRIDE 20           // 16 + 4 pad floats (16B-aligned rows)
#define SA_FLOATS (128 * SA_STRIDE)

template<int NCH, int MODE>
__global__ void __launch_bounds__(256, 1)
edge_gemm(const float* __restrict__ P0, const float* __restrict__ P1,
          const int* __restrict__ srcIdx, const float* __restrict__ W,
          const float* __restrict__ bias, float* __restrict__ outp) {
    constexpr int K = NCH * 16;
    extern __shared__ float sm[];
    float* sW  = sm;                       // [K][128]
    float* sA0 = sm + K * HH;              // [128][20]
    float* sA1 = sA0 + SA_FLOATS;
    __shared__ int s_src[128];

    const float* A0 = (MODE == 0) ? P0 : g_node;
    const float* A1 = (MODE == 0) ? P1 : g_eattr;
    float* dst      = (MODE == 0) ? g_eattr : outp;

    int tid = threadIdx.x;
    int tx = tid & 15, ty = tid >> 4;

    for (int i = tid; i < K * HH / 4; i += 256)
        ((float4*)sW)[i] = ((const float4*)W)[i];

    ull bias_p[4];
    #pragma unroll
    for (int p = 0; p < 4; p++)
        bias_p[p] = pack2(bias[tx * 8 + 2 * p], bias[tx * 8 + 2 * p + 1]);

    const int aBase = ty * 8 * SA_STRIDE;

    for (int tile = blockIdx.x; tile < NT_E; tile += gridDim.x) {
        int e0 = tile * 128;
        __syncthreads();                       // fence smem reuse from prev tile
        if (MODE == 1) { if (tid < 128) s_src[tid] = srcIdx[e0 + tid]; }
        __syncthreads();

        // ---- stage helper (inlined twice) ----
        #define STAGE(C, SBUF)                                                        \
        {                                                                             \
            int base_k = (C) * 16;                                                    \
            _Pragma("unroll")                                                         \
            for (int p = 0; p < 2; p++) {                                             \
                int idx = tid + p * 256;                                              \
                int e = idx >> 2, kk = (idx & 3) * 4;                                 \
                int gk = base_k + kk;                                                 \
                const float* gsrc;                                                    \
                if (MODE == 0)                                                        \
                    gsrc = (gk < EDD) ? (A0 + (size_t)(e0 + e) * EDD + gk)            \
                                      : (A1 + (size_t)(e0 + e) * DD2D + (gk - EDD));  \
                else                                                                  \
                    gsrc = (gk < HH) ? (A0 + (size_t)s_src[e] * HH + gk)              \
                                     : (A1 + (size_t)(e0 + e) * HH + (gk - HH));      \
                cp16((SBUF) + e * SA_STRIDE + kk, gsrc);                              \
            }                                                                         \
            CP_COMMIT();                                                              \
        }

        STAGE(0, sA0);
        CP_WAIT0();
        __syncthreads();

        ull acc[8][4];
        #pragma unroll
        for (int i = 0; i < 8; i++)
            #pragma unroll
            for (int p = 0; p < 4; p++) acc[i][p] = bias_p[p];

        for (int c = 0; c < NCH; c++) {
            float* cur = (c & 1) ? sA1 : sA0;
            float* nxt = (c & 1) ? sA0 : sA1;
            if (c + 1 < NCH) STAGE(c + 1, nxt);

            const float* sWc = sW + c * 16 * HH;
            #pragma unroll 4
            for (int kk = 0; kk < 16; kk++) {
                const ulonglong2 bA = *(const ulonglong2*)(sWc + kk * HH + tx * 8);
                const ulonglong2 bB = *(const ulonglong2*)(sWc + kk * HH + tx * 8 + 4);
                const float* ac = cur + aBase + kk;
                #pragma unroll
                for (int i = 0; i < 8; i++) {
                    float av = ac[i * SA_STRIDE];
                    ull ad = pack2(av, av);
                    acc[i][0] = fma2(ad, bA.x, acc[i][0]);
                    acc[i][1] = fma2(ad, bA.y, acc[i][1]);
                    acc[i][2] = fma2(ad, bB.x, acc[i][2]);
                    acc[i][3] = fma2(ad, bB.y, acc[i][3]);
                }
            }
            if (c + 1 < NCH) CP_WAIT0();
            __syncthreads();
        }
        #undef STAGE

        // epilogue: gelu + vectorized store
        #pragma unroll
        for (int i = 0; i < 8; i++) {
            float v[8];
            #pragma unroll
            for (int p = 0; p < 4; p++) unpack2(acc[i][p], v[2 * p], v[2 * p + 1]);
            float4 o0 = make_float4(gelu_f(v[0]), gelu_f(v[1]), gelu_f(v[2]), gelu_f(v[3]));
            float4 o1 = make_float4(gelu_f(v[4]), gelu_f(v[5]), gelu_f(v[6]), gelu_f(v[7]));
            size_t row = (size_t)(e0 + ty * 8 + i) * HH + tx * 8;
            *(float4*)(dst + row)     = o0;
            *(float4*)(dst + row + 4) = o1;
        }
    }
}

#define SMEM_E1 ((192 * 128 + 2 * SA_FLOATS) * 4)   // 118,784 B
#define SMEM_E2 ((256 * 128 + 2 * SA_FLOATS) * 4)   // 151,552 B

// ======================================================================
// launch
// ======================================================================
extern "C" void kernel_launch(void* const* d_in, const int* in_sizes, int n_in,
                              void* d_out, int out_size) {
    const int*   atomic_numbers = (const int*)  d_in[0];
    const float* nde            = (const float*)d_in[1];
    const float* edist          = (const float*)d_in[2];
    const float* edir           = (const float*)d_in[3];
    const int*   charge         = (const int*)  d_in[4];
    const int*   spin           = (const int*)  d_in[5];
    const int*   nbatch         = (const int*)  d_in[6];
    const int*   nsrc           = (const int*)  d_in[7];
    const float* emb_atom       = (const float*)d_in[8];
    const float* W_nd           = (const float*)d_in[9];
    const float* b_nd           = (const float*)d_in[10];
    const float* ln_g           = (const float*)d_in[11];
    const float* ln_b           = (const float*)d_in[12];
    const float* W_node         = (const float*)d_in[13];
    const float* b_node         = (const float*)d_in[14];
    const float* emb_chg        = (const float*)d_in[15];
    const float* emb_spin       = (const float*)d_in[16];
    const float* W_cs           = (const float*)d_in[17];
    const float* b_cs           = (const float*)d_in[18];
    const float* W_edge         = (const float*)d_in[19];
    const float* b_edge         = (const float*)d_in[20];
    const float* W_ef           = (const float*)d_in[21];
    const float* b_ef           = (const float*)d_in[22];
    float* out = (float*)d_out;

    cudaFuncSetAttribute(node_kernel,    cudaFuncAttributeMaxDynamicSharedMemorySize, SMEM_NODE);
    cudaFuncSetAttribute(edge_gemm<12, 0>, cudaFuncAttributeMaxDynamicSharedMemorySize, SMEM_E1);
    cudaFuncSetAttribute(edge_gemm<16, 1>, cudaFuncAttributeMaxDynamicSharedMemorySize, SMEM_E2);

    int nsm = 148;
    cudaDeviceGetAttribute(&nsm, cudaDevAttrMultiProcessorCount, 0);

    cs_kernel<<<NG, HH>>>(charge, spin, emb_chg, emb_spin, W_cs, b_cs);
    node_kernel<<<nsm, 256, SMEM_NODE>>>(atomic_numbers, nde, nbatch, emb_atom,
                                         W_nd, b_nd, ln_g, ln_b, W_node, b_node);
    edge_gemm<12, 0><<<nsm, 256, SMEM_E1>>>(edist, edir, nullptr, W_edge, b_edge, nullptr);
    edge_gemm<16, 1><<<nsm, 256, SMEM_E2>>>(nullptr, nullptr, nsrc, W_ef, b_ef, out);
}

// round 3
// speedup vs baseline: 1.5402x; 1.5402x over previous
#include <cuda_runtime.h>
#include <cuda_bf16.h>
#include <cstdint>
#include <cstddef>

// ---------------- problem constants ----------------
#define NN     50000
#define NE     800000
#define NG     32
#define HH     128
#define NDD    16
#define EDD    128
#define DD2D   64

#define NT_E   (NE/128)     // 6250 edge tiles of 128
#define NT_N   (NN/16)      // 3125 node tiles of 16

// ---------------- scratch (device globals: no allocation allowed) ----------------
__device__ float g_cs[NG * HH];
__device__ float g_node[(size_t)NN * HH];
__device__ float g_eattr[(size_t)NE * HH];

// ---------------- helpers ----------------
__device__ __forceinline__ float gelu_f(float x) {
    return 0.5f * x * (1.0f + erff(x * 0.70710678118654752440f));
}

__device__ __forceinline__ uint32_t smem_u32(const void* p) {
    return (uint32_t)__cvta_generic_to_shared(p);
}

// pack two f32 -> bf16x2 (lo half = a, hi half = b)
__device__ __forceinline__ uint32_t cvt2(float a, float b) {
    uint32_t r;
    asm("cvt.rn.bf16x2.f32 %0, %1, %2;" : "=r"(r) : "f"(b), "f"(a));
    return r;
}

__device__ __forceinline__ void ldsm4(uint32_t r[4], uint32_t addr) {
    asm volatile("ldmatrix.sync.aligned.m8n8.x4.shared.b16 {%0,%1,%2,%3}, [%4];"
                 : "=r"(r[0]), "=r"(r[1]), "=r"(r[2]), "=r"(r[3]) : "r"(addr));
}

__device__ __forceinline__ void mma_bf16(float c[4], const uint32_t a[4],
                                         uint32_t b0, uint32_t b1) {
    asm volatile("mma.sync.aligned.m16n8k16.row.col.f32.bf16.bf16.f32 "
                 "{%0,%1,%2,%3}, {%4,%5,%6,%7}, {%8,%9}, {%0,%1,%2,%3};"
                 : "+f"(c[0]), "+f"(c[1]), "+f"(c[2]), "+f"(c[3])
                 : "r"(a[0]), "r"(a[1]), "r"(a[2]), "r"(a[3]), "r"(b0), "r"(b1));
}

// ======================================================================
// Kernel 0: cs[g] = gelu(concat(emb_chg[charge], emb_spin[spin]) @ W_cs + b_cs)
// ======================================================================
__global__ void cs_kernel(const int* __restrict__ charge, const int* __restrict__ spin,
                          const float* __restrict__ emb_chg, const float* __restrict__ emb_spin,
                          const float* __restrict__ W_cs, const float* __restrict__ b_cs) {
    __shared__ float xv[2 * HH];
    int g = blockIdx.x, j = threadIdx.x;
    int c = charge[g], s = spin[g];
    xv[j]      = emb_chg[c * HH + j];
    xv[HH + j] = emb_spin[s * HH + j];
    __syncthreads();
    float acc = b_cs[j];
    #pragma unroll 8
    for (int k = 0; k < 2 * HH; k++) acc += xv[k] * W_cs[k * HH + j];
    g_cs[g * HH + j] = gelu_f(acc);
}

// ======================================================================
// Kernel 1: node features (persistent; W_node resident in smem) — fp32 path
// ======================================================================
#define SX_STRIDE 257
#define SMEM_NODE ((32768 + 16 * SX_STRIDE) * 4)

__global__ void __launch_bounds__(256, 1)
node_kernel(const int* __restrict__ an, const float* __restrict__ nde,
            const int* __restrict__ nbatch,
            const float* __restrict__ emb_atom, const float* __restrict__ W_nd,
            const float* __restrict__ b_nd, const float* __restrict__ ln_g,
            const float* __restrict__ ln_b, const float* __restrict__ W_node,
            const float* __restrict__ b_node) {
    extern __shared__ float sm[];
    float* sW = sm;                  // [256][128]
    float* sx = sm + 32768;          // [16][257]
    __shared__ float smu[16], srs[16];
    int tid = threadIdx.x;

    for (int i = tid; i < 32768 / 4; i += 256)
        ((float4*)sW)[i] = ((const float4*)W_node)[i];

    for (int t0 = blockIdx.x; t0 < NT_N; t0 += gridDim.x) {
        __syncthreads();
        int n0 = t0 * 16;
        for (int idx = tid; idx < 16 * HH; idx += 256) {
            int n = idx >> 7, j = idx & 127;
            int node = n0 + n;
            float a = emb_atom[an[node] * HH + j];
            float accv = b_nd[j];
            const float* nrow = nde + node * NDD;
            #pragma unroll
            for (int k = 0; k < NDD; k++) accv += nrow[k] * W_nd[k * HH + j];
            sx[n * SX_STRIDE + j]      = a;
            sx[n * SX_STRIDE + HH + j] = gelu_f(accv);
        }
        __syncthreads();
        int w = tid >> 5, lane = tid & 31;
        for (int n = w; n < 16; n += 8) {
            float s1 = 0.f, s2 = 0.f;
            for (int k = lane; k < 256; k += 32) {
                float v = sx[n * SX_STRIDE + k]; s1 += v; s2 += v * v;
            }
            #pragma unroll
            for (int o = 16; o > 0; o >>= 1) {
                s1 += __shfl_down_sync(0xffffffffu, s1, o);
                s2 += __shfl_down_sync(0xffffffffu, s2, o);
            }
            if (lane == 0) {
                float mu  = s1 * (1.f / 256.f);
                float var = s2 * (1.f / 256.f) - mu * mu;
                smu[n] = mu; srs[n] = rsqrtf(var + 1e-5f);
            }
        }
        __syncthreads();
        for (int idx = tid; idx < 16 * 256; idx += 256) {
            int n = idx >> 8, k = idx & 255;
            sx[n * SX_STRIDE + k] =
                (sx[n * SX_STRIDE + k] - smu[n]) * srs[n] * ln_g[k] + ln_b[k];
        }
        __syncthreads();
        {
            int n = tid >> 4, jb = tid & 15;
            float acc[8];
            #pragma unroll
            for (int q = 0; q < 8; q++) acc[q] = b_node[jb * 8 + q];
            const float* xr = sx + n * SX_STRIDE;
            #pragma unroll 4
            for (int k = 0; k < 256; k++) {
                float a = xr[k];
                const float4 b0 = *(const float4*)&sW[k * HH + jb * 8];
                const float4 b1 = *(const float4*)&sW[k * HH + jb * 8 + 4];
                acc[0] += a * b0.x; acc[1] += a * b0.y; acc[2] += a * b0.z; acc[3] += a * b0.w;
                acc[4] += a * b1.x; acc[5] += a * b1.y; acc[6] += a * b1.z; acc[7] += a * b1.w;
            }
            int node = n0 + n;
            const float* csr = g_cs + nbatch[node] * HH;
            float4 o0, o1;
            o0.x = gelu_f(acc[0]) + csr[jb * 8 + 0];
            o0.y = gelu_f(acc[1]) + csr[jb * 8 + 1];
            o0.z = gelu_f(acc[2]) + csr[jb * 8 + 2];
            o0.w = gelu_f(acc[3]) + csr[jb * 8 + 3];
            o1.x = gelu_f(acc[4]) + csr[jb * 8 + 4];
            o1.y = gelu_f(acc[5]) + csr[jb * 8 + 5];
            o1.z = gelu_f(acc[6]) + csr[jb * 8 + 6];
            o1.w = gelu_f(acc[7]) + csr[jb * 8 + 7];
            *(float4*)&g_node[(size_t)node * HH + jb * 8]     = o0;
            *(float4*)&g_node[(size_t)node * HH + jb * 8 + 4] = o1;
        }
    }
}

// ======================================================================
// Edge GEMMs via warp-level bf16 HMMA (mma.sync m16n8k16), hi/lo 3-pass split
//   MODE 0: eattr = gelu([edist|edir] @ W_edge + b)          K=192
//   MODE 1: out   = gelu([node[src]|eattr] @ W_ef + b)       K=256
//
// Tile: 128 edges x 128 cols. 8 warps in 4(m) x 2(n): warp = 32 rows x 64 cols.
// W resident in smem transposed [n][k] bf16 hi+lo (padded stride KS).
// A staged per 64-k chunk: LDG fp32 -> reg split -> STS bf16 hi+lo, double buffer.
// ======================================================================
template<int KDIM, int MODE>
__global__ void __launch_bounds__(256, 1)
edge_hmma(const float* __restrict__ P0, const float* __restrict__ P1,
          const int* __restrict__ srcIdx, const float* __restrict__ W,
          const float* __restrict__ bias, float* __restrict__ outp)
{
    constexpr int KS     = KDIM + 8;       // W smem stride (bf16 elems)
    constexpr int AS     = 72;             // A chunk row stride (bf16 elems)
    constexpr int NC     = KDIM / 64;      // 64-k chunks
    constexpr int W_PART = 128 * KS;       // elems per W part
    constexpr int A_PART = 128 * AS;       // elems per A part (one buffer)

    extern __shared__ __nv_bfloat16 sb[];
    __nv_bfloat16* sWhi = sb;
    __nv_bfloat16* sWlo = sb + W_PART;
    __nv_bfloat16* sA   = sb + 2 * W_PART;   // [buf][part][128][AS]

    float* dst = (MODE == 0) ? g_eattr : outp;

    const int tid = threadIdx.x, lane = tid & 31, wid = tid >> 5;
    const int warp_m = wid & 3, warp_n = wid >> 2;

    // ---- build W transposed hi/lo (once per CTA) ----
    {
        int n = tid & 127;
        for (int k = tid >> 7; k < KDIM; k += 2) {
            float w = W[(size_t)k * HH + n];
            __nv_bfloat16 h = __float2bfloat16(w);
            __nv_bfloat16 l = __float2bfloat16(w - __bfloat162float(h));
            sWhi[n * KS + k] = h;
            sWlo[n * KS + k] = l;
        }
    }
    __syncthreads();

    // lane constants
    const int lrow = (lane & 7) + ((lane >> 3) & 1) * 8;  // ldmatrix row 0..15
    const int lkh  = lane >> 4;                           // ldmatrix k-half
    const int bn   = lane >> 2;                           // B frag n within 8
    const int bk   = (lane & 3) * 2;                      // B frag k within 8
    const int arow = tid >> 1, ahalf = tid & 1;           // A staging row/half

    const uint32_t sA_u32 = smem_u32(sA);
    const uint32_t a_lane_off =
        (uint32_t)(((warp_m * 32 + lrow) * AS + lkh * 8) * 2);

    float4 v[8];

    for (int tile = blockIdx.x; tile < NT_E; tile += gridDim.x) {
        const int e0 = tile * 128;
        const int ee = e0 + arow;
        size_t srow = 0;
        if (MODE == 1) srow = (size_t)srcIdx[ee];

        // ---- chunk loader (32 contiguous floats per thread) ----
        auto loadc = [&](int c) {
            const int gk0 = c * 64 + ahalf * 32;
            const float* p;
            if (MODE == 0)
                p = (gk0 < EDD) ? P0 + (size_t)ee * EDD + gk0
                                : P1 + (size_t)ee * DD2D + (gk0 - EDD);
            else
                p = (gk0 < HH) ? g_node + srow * HH + gk0
                               : g_eattr + (size_t)ee * HH + (gk0 - HH);
            #pragma unroll
            for (int i = 0; i < 8; i++) v[i] = ((const float4*)p)[i];
        };
        auto stsc = [&](int buf) {
            uint32_t hi[16], lo[16];
            #pragma unroll
            for (int i = 0; i < 8; i++) {
                uint32_t hp0 = cvt2(v[i].x, v[i].y);
                float a0 = __uint_as_float(hp0 << 16);
                float a1 = __uint_as_float(hp0 & 0xFFFF0000u);
                uint32_t lp0 = cvt2(v[i].x - a0, v[i].y - a1);
                uint32_t hp1 = cvt2(v[i].z, v[i].w);
                float a2 = __uint_as_float(hp1 << 16);
                float a3 = __uint_as_float(hp1 & 0xFFFF0000u);
                uint32_t lp1 = cvt2(v[i].z - a2, v[i].w - a3);
                hi[2 * i] = hp0; hi[2 * i + 1] = hp1;
                lo[2 * i] = lp0; lo[2 * i + 1] = lp1;
            }
            __nv_bfloat16* bh = sA + buf * 2 * A_PART + arow * AS + ahalf * 32;
            __nv_bfloat16* bl = bh + A_PART;
            #pragma unroll
            for (int j = 0; j < 4; j++) {
                *(uint4*)(bh + j * 8) =
                    make_uint4(hi[4 * j], hi[4 * j + 1], hi[4 * j + 2], hi[4 * j + 3]);
                *(uint4*)(bl + j * 8) =
                    make_uint4(lo[4 * j], lo[4 * j + 1], lo[4 * j + 2], lo[4 * j + 3]);
            }
        };

        __syncthreads();             // buf0 free from previous tile
        loadc(0);
        stsc(0);

        // ---- init accumulators with bias ----
        float acc[2][8][4];
        #pragma unroll
        for (int nb = 0; nb < 8; nb++) {
            float b0 = bias[warp_n * 64 + nb * 8 + bk];
            float b1 = bias[warp_n * 64 + nb * 8 + bk + 1];
            #pragma unroll
            for (int mb = 0; mb < 2; mb++) {
                acc[mb][nb][0] = b0; acc[mb][nb][1] = b1;
                acc[mb][nb][2] = b0; acc[mb][nb][3] = b1;
            }
        }
        __syncthreads();

        // ---- main loop over 64-k chunks ----
        for (int c = 0; c < NC; c++) {
            if (c + 1 < NC) loadc(c + 1);

            const uint32_t abase = sA_u32 + (uint32_t)(c & 1) * (2 * A_PART * 2) + a_lane_off;
            #pragma unroll
            for (int ks = 0; ks < 4; ks++) {
                uint32_t ah0[4], ah1[4], al0[4], al1[4];
                const uint32_t ao = abase + ks * 32;
                ldsm4(ah0, ao);
                ldsm4(ah1, ao + 16 * AS * 2);
                ldsm4(al0, ao + A_PART * 2);
                ldsm4(al1, ao + A_PART * 2 + 16 * AS * 2);
                const int kg = c * 64 + ks * 16;
                #pragma unroll
                for (int nb = 0; nb < 8; nb++) {
                    const __nv_bfloat16* wp =
                        sWhi + (warp_n * 64 + nb * 8 + bn) * KS + kg + bk;
                    uint32_t bh0 = *(const uint32_t*)wp;
                    uint32_t bh1 = *(const uint32_t*)(wp + 8);
                    uint32_t bl0 = *(const uint32_t*)(wp + W_PART);
                    uint32_t bl1 = *(const uint32_t*)(wp + W_PART + 8);
                    mma_bf16(acc[0][nb], ah0, bh0, bh1);
                    mma_bf16(acc[1][nb], ah1, bh0, bh1);
                    mma_bf16(acc[0][nb], ah0, bl0, bl1);
                    mma_bf16(acc[1][nb], ah1, bl0, bl1);
                    mma_bf16(acc[0][nb], al0, bh0, bh1);
                    mma_bf16(acc[1][nb], al1, bh0, bh1);
                }
            }

            if (c + 1 < NC) {
                stsc((c + 1) & 1);
                __syncthreads();
            }
        }

        // ---- epilogue: gelu + store ----
        #pragma unroll
        for (int mb = 0; mb < 2; mb++) {
            const int rg = e0 + warp_m * 32 + mb * 16 + (lane >> 2);
            #pragma unroll
            for (int nb = 0; nb < 8; nb++) {
                const int col = warp_n * 64 + nb * 8 + bk;
                float2 o0, o1;
                o0.x = gelu_f(acc[mb][nb][0]);
                o0.y = gelu_f(acc[mb][nb][1]);
                o1.x = gelu_f(acc[mb][nb][2]);
                o1.y = gelu_f(acc[mb][nb][3]);
                *(float2*)(dst + (size_t)rg * HH + col)       = o0;
                *(float2*)(dst + (size_t)(rg + 8) * HH + col) = o1;
            }
        }
    }
}

#define SMEM_E1 ((2 * 128 * (192 + 8) + 4 * 128 * 72) * 2)   // 176,128 B
#define SMEM_E2 ((2 * 128 * (256 + 8) + 4 * 128 * 72) * 2)   // 208,896 B

// ======================================================================
// launch
// ======================================================================
extern "C" void kernel_launch(void* const* d_in, const int* in_sizes, int n_in,
                              void* d_out, int out_size) {
    const int*   atomic_numbers = (const int*)  d_in[0];
    const float* nde            = (const float*)d_in[1];
    const float* edist          = (const float*)d_in[2];
    const float* edir           = (const float*)d_in[3];
    const int*   charge         = (const int*)  d_in[4];
    const int*   spin           = (const int*)  d_in[5];
    const int*   nbatch         = (const int*)  d_in[6];
    const int*   nsrc           = (const int*)  d_in[7];
    const float* emb_atom       = (const float*)d_in[8];
    const float* W_nd           = (const float*)d_in[9];
    const float* b_nd           = (const float*)d_in[10];
    const float* ln_g           = (const float*)d_in[11];
    const float* ln_b           = (const float*)d_in[12];
    const float* W_node         = (const float*)d_in[13];
    const float* b_node         = (const float*)d_in[14];
    const float* emb_chg        = (const float*)d_in[15];
    const float* emb_spin       = (const float*)d_in[16];
    const float* W_cs           = (const float*)d_in[17];
    const float* b_cs           = (const float*)d_in[18];
    const float* W_edge         = (const float*)d_in[19];
    const float* b_edge         = (const float*)d_in[20];
    const float* W_ef           = (const float*)d_in[21];
    const float* b_ef           = (const float*)d_in[22];
    float* out = (float*)d_out;

    cudaFuncSetAttribute(node_kernel, cudaFuncAttributeMaxDynamicSharedMemorySize, SMEM_NODE);
    cudaFuncSetAttribute(edge_hmma<192, 0>, cudaFuncAttributeMaxDynamicSharedMemorySize, SMEM_E1);
    cudaFuncSetAttribute(edge_hmma<256, 1>, cudaFuncAttributeMaxDynamicSharedMemorySize, SMEM_E2);

    int nsm = 148;
    cudaDeviceGetAttribute(&nsm, cudaDevAttrMultiProcessorCount, 0);

    cs_kernel<<<NG, HH>>>(charge, spin, emb_chg, emb_spin, W_cs, b_cs);
    node_kernel<<<nsm, 256, SMEM_NODE>>>(atomic_numbers, nde, nbatch, emb_atom,
                                         W_nd, b_nd, ln_g, ln_b, W_node, b_node);
    edge_hmma<192, 0><<<nsm, 256, SMEM_E1>>>(edist, edir, nullptr, W_edge, b_edge, nullptr);
    edge_hmma<256, 1><<<nsm, 256, SMEM_E2>>>(nullptr, nullptr, nsrc, W_ef, b_ef, out);
}

// round 4
// speedup vs baseline: 1.9957x; 1.2958x over previous
#include <cuda_runtime.h>
#include <cuda_bf16.h>
#include <cstdint>
#include <cstddef>

// ---------------- problem constants ----------------
#define NN     50000
#define NE     800000
#define NG     32
#define HH     128
#define NDD    16
#define EDD    128
#define DD2D   64

#define NT_E   (NE/128)     // 6250 edge tiles of 128
#define NT_N   (NN/16)      // 3125 node tiles of 16

// ---------------- scratch (device globals: no allocation allowed) ----------------
__device__ float g_cs[NG * HH];
__device__ float g_node[(size_t)NN * HH];
__device__ float g_eattr[(size_t)NE * HH];

// ---------------- helpers ----------------
__device__ __forceinline__ float gelu_f(float x) {
    return 0.5f * x * (1.0f + erff(x * 0.70710678118654752440f));
}

// pack two f32 -> bf16x2 (lo half = a, hi half = b)
__device__ __forceinline__ uint32_t cvt2(float a, float b) {
    uint32_t r;
    asm("cvt.rn.bf16x2.f32 %0, %1, %2;" : "=r"(r) : "f"(b), "f"(a));
    return r;
}

// split a float2 pair into hi bf16x2 and lo bf16x2
__device__ __forceinline__ void split2(float2 v, uint32_t& hi, uint32_t& lo) {
    hi = cvt2(v.x, v.y);
    float fa = __uint_as_float(hi << 16);
    float fb = __uint_as_float(hi & 0xFFFF0000u);
    lo = cvt2(v.x - fa, v.y - fb);
}

__device__ __forceinline__ void mma_bf16(float c[4], const uint32_t a[4],
                                         uint32_t b0, uint32_t b1) {
    asm volatile("mma.sync.aligned.m16n8k16.row.col.f32.bf16.bf16.f32 "
                 "{%0,%1,%2,%3}, {%4,%5,%6,%7}, {%8,%9}, {%0,%1,%2,%3};"
                 : "+f"(c[0]), "+f"(c[1]), "+f"(c[2]), "+f"(c[3])
                 : "r"(a[0]), "r"(a[1]), "r"(a[2]), "r"(a[3]), "r"(b0), "r"(b1));
}

// ======================================================================
// Kernel 0: cs[g] = gelu(concat(emb_chg[charge], emb_spin[spin]) @ W_cs + b_cs)
// ======================================================================
__global__ void cs_kernel(const int* __restrict__ charge, const int* __restrict__ spin,
                          const float* __restrict__ emb_chg, const float* __restrict__ emb_spin,
                          const float* __restrict__ W_cs, const float* __restrict__ b_cs) {
    __shared__ float xv[2 * HH];
    int g = blockIdx.x, j = threadIdx.x;
    int c = charge[g], s = spin[g];
    xv[j]      = emb_chg[c * HH + j];
    xv[HH + j] = emb_spin[s * HH + j];
    __syncthreads();
    float acc = b_cs[j];
    #pragma unroll 8
    for (int k = 0; k < 2 * HH; k++) acc += xv[k] * W_cs[k * HH + j];
    g_cs[g * HH + j] = gelu_f(acc);
}

// ======================================================================
// Kernel 1: node features (persistent; W_node resident in smem) — fp32 path
// ======================================================================
#define SX_STRIDE 257
#define SMEM_NODE ((32768 + 16 * SX_STRIDE) * 4)

__global__ void __launch_bounds__(256, 1)
node_kernel(const int* __restrict__ an, const float* __restrict__ nde,
            const int* __restrict__ nbatch,
            const float* __restrict__ emb_atom, const float* __restrict__ W_nd,
            const float* __restrict__ b_nd, const float* __restrict__ ln_g,
            const float* __restrict__ ln_b, const float* __restrict__ W_node,
            const float* __restrict__ b_node) {
    extern __shared__ float sm[];
    float* sW = sm;                  // [256][128]
    float* sx = sm + 32768;          // [16][257]
    __shared__ float smu[16], srs[16];
    int tid = threadIdx.x;

    for (int i = tid; i < 32768 / 4; i += 256)
        ((float4*)sW)[i] = ((const float4*)W_node)[i];

    for (int t0 = blockIdx.x; t0 < NT_N; t0 += gridDim.x) {
        __syncthreads();
        int n0 = t0 * 16;
        for (int idx = tid; idx < 16 * HH; idx += 256) {
            int n = idx >> 7, j = idx & 127;
            int node = n0 + n;
            float a = emb_atom[an[node] * HH + j];
            float accv = b_nd[j];
            const float* nrow = nde + node * NDD;
            #pragma unroll
            for (int k = 0; k < NDD; k++) accv += nrow[k] * W_nd[k * HH + j];
            sx[n * SX_STRIDE + j]      = a;
            sx[n * SX_STRIDE + HH + j] = gelu_f(accv);
        }
        __syncthreads();
        int w = tid >> 5, lane = tid & 31;
        for (int n = w; n < 16; n += 8) {
            float s1 = 0.f, s2 = 0.f;
            for (int k = lane; k < 256; k += 32) {
                float v = sx[n * SX_STRIDE + k]; s1 += v; s2 += v * v;
            }
            #pragma unroll
            for (int o = 16; o > 0; o >>= 1) {
                s1 += __shfl_down_sync(0xffffffffu, s1, o);
                s2 += __shfl_down_sync(0xffffffffu, s2, o);
            }
            if (lane == 0) {
                float mu  = s1 * (1.f / 256.f);
                float var = s2 * (1.f / 256.f) - mu * mu;
                smu[n] = mu; srs[n] = rsqrtf(var + 1e-5f);
            }
        }
        __syncthreads();
        for (int idx = tid; idx < 16 * 256; idx += 256) {
            int n = idx >> 8, k = idx & 255;
            sx[n * SX_STRIDE + k] =
                (sx[n * SX_STRIDE + k] - smu[n]) * srs[n] * ln_g[k] + ln_b[k];
        }
        __syncthreads();
        {
            int n = tid >> 4, jb = tid & 15;
            float acc[8];
            #pragma unroll
            for (int q = 0; q < 8; q++) acc[q] = b_node[jb * 8 + q];
            const float* xr = sx + n * SX_STRIDE;
            #pragma unroll 4
            for (int k = 0; k < 256; k++) {
                float a = xr[k];
                const float4 b0 = *(const float4*)&sW[k * HH + jb * 8];
                const float4 b1 = *(const float4*)&sW[k * HH + jb * 8 + 4];
                acc[0] += a * b0.x; acc[1] += a * b0.y; acc[2] += a * b0.z; acc[3] += a * b0.w;
                acc[4] += a * b1.x; acc[5] += a * b1.y; acc[6] += a * b1.z; acc[7] += a * b1.w;
            }
            int node = n0 + n;
            const float* csr = g_cs + nbatch[node] * HH;
            float4 o0, o1;
            o0.x = gelu_f(acc[0]) + csr[jb * 8 + 0];
            o0.y = gelu_f(acc[1]) + csr[jb * 8 + 1];
            o0.z = gelu_f(acc[2]) + csr[jb * 8 + 2];
            o0.w = gelu_f(acc[3]) + csr[jb * 8 + 3];
            o1.x = gelu_f(acc[4]) + csr[jb * 8 + 4];
            o1.y = gelu_f(acc[5]) + csr[jb * 8 + 5];
            o1.z = gelu_f(acc[6]) + csr[jb * 8 + 6];
            o1.w = gelu_f(acc[7]) + csr[jb * 8 + 7];
            *(float4*)&g_node[(size_t)node * HH + jb * 8]     = o0;
            *(float4*)&g_node[(size_t)node * HH + jb * 8 + 4] = o1;
        }
    }
}

// ======================================================================
// Edge GEMMs via warp-level bf16 HMMA, hi/lo 3-pass split.
// Warp tiling 8(m) x 1(n): warp = 16 rows x 128 cols.
// A: gmem -> registers directly (fragment-shaped LDG.64, prefetch 1 kstep).
// W: smem-resident transposed [n][k] bf16 hi+lo, stride KDIM+8 (conflict-free).
// NO __syncthreads in the main loop — warps run decoupled.
//   MODE 0: eattr = gelu([edist|edir] @ W_edge + b)          K=192
//   MODE 1: out   = gelu([node[src]|eattr] @ W_ef + b)       K=256
// ======================================================================
template<int KDIM, int MODE>
__global__ void __launch_bounds__(256, 1)
edge_hmma(const float* __restrict__ P0, const float* __restrict__ P1,
          const int* __restrict__ srcIdx, const float* __restrict__ W,
          const float* __restrict__ bias, float* __restrict__ outp)
{
    constexpr int KS     = KDIM + 8;       // W smem stride (bf16 elems)
    constexpr int NKS    = KDIM / 16;      // k-steps
    constexpr int W_PART = 128 * KS;       // elems per W part

    extern __shared__ __nv_bfloat16 sb[];
    __nv_bfloat16* sWhi = sb;
    __nv_bfloat16* sWlo = sb + W_PART;

    float* dst = (MODE == 0) ? g_eattr : outp;

    const int tid = threadIdx.x, lane = tid & 31, wid = tid >> 5;

    // ---- build W transposed hi/lo (once per CTA) ----
    {
        int n = tid & 127;
        for (int k = tid >> 7; k < KDIM; k += 2) {
            float w = W[(size_t)k * HH + n];
            __nv_bfloat16 h = __float2bfloat16(w);
            __nv_bfloat16 l = __float2bfloat16(w - __bfloat162float(h));
            sWhi[n * KS + k] = h;
            sWlo[n * KS + k] = l;
        }
    }
    __syncthreads();

    const int lr = lane >> 2;           // fragment row 0..7
    const int kc = (lane & 3) * 2;      // fragment k pair base

    // bias fragment (cols nb*8 + kc, +1)
    float2 bfr[16];
    #pragma unroll
    for (int nb = 0; nb < 16; nb++)
        bfr[nb] = *(const float2*)(bias + nb * 8 + kc);

    // B smem row base for this lane: col n = nb*8 + lr, k offset kc
    const __nv_bfloat16* wbase_hi = sWhi + (size_t)lr * KS + kc;
    const __nv_bfloat16* wbase_lo = sWlo + (size_t)lr * KS + kc;

    for (int tile = blockIdx.x; tile < NT_E; tile += gridDim.x) {
        const int e0 = tile * 128;
        const int r0 = e0 + wid * 16 + lr;   // global row (edge) 0
        const int r1 = r0 + 8;               // global row (edge) 1

        // region base pointers (already offset by kc)
        const float *pa0, *pb0, *pa1, *pb1;
        if (MODE == 0) {
            pa0 = P0 + (size_t)r0 * EDD + kc;  pb0 = P1 + (size_t)r0 * DD2D + kc;
            pa1 = P0 + (size_t)r1 * EDD + kc;  pb1 = P1 + (size_t)r1 * DD2D + kc;
        } else {
            pa0 = g_node + (size_t)srcIdx[r0] * HH + kc;  pb0 = g_eattr + (size_t)r0 * HH + kc;
            pa1 = g_node + (size_t)srcIdx[r1] * HH + kc;  pb1 = g_eattr + (size_t)r1 * HH + kc;
        }

        // accumulators: 16 n-blocks x 4
        float acc[16][4];
        #pragma unroll
        for (int nb = 0; nb < 16; nb++) {
            acc[nb][0] = bfr[nb].x; acc[nb][1] = bfr[nb].y;
            acc[nb][2] = bfr[nb].x; acc[nb][3] = bfr[nb].y;
        }

        // A fragment loader: v[0]=row0@k, v[1]=row1@k, v[2]=row0@k+8, v[3]=row1@k+8
        float2 v[4], vn[4];
        #define LOADA(KG, VV)                                                     \
        {                                                                         \
            const float* q0 = ((KG) < 128) ? pa0 + (KG) : pb0 + ((KG) - 128);     \
            const float* q1 = ((KG) < 128) ? pa1 + (KG) : pb1 + ((KG) - 128);     \
            (VV)[0] = *(const float2*)(q0);                                       \
            (VV)[1] = *(const float2*)(q1);                                       \
            (VV)[2] = *(const float2*)(q0 + 8);                                   \
            (VV)[3] = *(const float2*)(q1 + 8);                                   \
        }

        LOADA(0, v);

        #pragma unroll
        for (int ks = 0; ks < NKS; ks++) {
            const int kg = ks * 16;
            if (ks + 1 < NKS) LOADA(kg + 16, vn);

            // split A fragments
            uint32_t ah[4], al[4];
            #pragma unroll
            for (int i = 0; i < 4; i++) split2(v[i], ah[i], al[i]);

            // load B hi fragments (16 nb x 2 regs)
            uint32_t bh[16][2];
            #pragma unroll
            for (int nb = 0; nb < 16; nb++) {
                const __nv_bfloat16* wp = wbase_hi + (size_t)nb * 8 * KS + kg;
                bh[nb][0] = *(const uint32_t*)wp;
                bh[nb][1] = *(const uint32_t*)(wp + 8);
            }
            // pass 1: hi x Whi — 16 independent accumulators
            #pragma unroll
            for (int nb = 0; nb < 16; nb++) mma_bf16(acc[nb], ah, bh[nb][0], bh[nb][1]);
            // pass 2: lo x Whi
            #pragma unroll
            for (int nb = 0; nb < 16; nb++) mma_bf16(acc[nb], al, bh[nb][0], bh[nb][1]);
            // load B lo fragments, pass 3: hi x Wlo
            uint32_t bl[16][2];
            #pragma unroll
            for (int nb = 0; nb < 16; nb++) {
                const __nv_bfloat16* wp = wbase_lo + (size_t)nb * 8 * KS + kg;
                bl[nb][0] = *(const uint32_t*)wp;
                bl[nb][1] = *(const uint32_t*)(wp + 8);
            }
            #pragma unroll
            for (int nb = 0; nb < 16; nb++) mma_bf16(acc[nb], ah, bl[nb][0], bl[nb][1]);

            if (ks + 1 < NKS) {
                #pragma unroll
                for (int i = 0; i < 4; i++) v[i] = vn[i];
            }
        }
        #undef LOADA

        // ---- epilogue: gelu + store (rows r0, r1; cols nb*8+kc) ----
        #pragma unroll
        for (int nb = 0; nb < 16; nb++) {
            const int col = nb * 8 + kc;
            float2 o0, o1;
            o0.x = gelu_f(acc[nb][0]);
            o0.y = gelu_f(acc[nb][1]);
            o1.x = gelu_f(acc[nb][2]);
            o1.y = gelu_f(acc[nb][3]);
            *(float2*)(dst + (size_t)r0 * HH + col) = o0;
            *(float2*)(dst + (size_t)r1 * HH + col) = o1;
        }
    }
}

#define SMEM_E1 (2 * 128 * (192 + 8) * 2)   // 102,400 B
#define SMEM_E2 (2 * 128 * (256 + 8) * 2)   // 135,168 B

// ======================================================================
// launch
// ======================================================================
extern "C" void kernel_launch(void* const* d_in, const int* in_sizes, int n_in,
                              void* d_out, int out_size) {
    const int*   atomic_numbers = (const int*)  d_in[0];
    const float* nde            = (const float*)d_in[1];
    const float* edist          = (const float*)d_in[2];
    const float* edir           = (const float*)d_in[3];
    const int*   charge         = (const int*)  d_in[4];
    const int*   spin           = (const int*)  d_in[5];
    const int*   nbatch         = (const int*)  d_in[6];
    const int*   nsrc           = (const int*)  d_in[7];
    const float* emb_atom       = (const float*)d_in[8];
    const float* W_nd           = (const float*)d_in[9];
    const float* b_nd           = (const float*)d_in[10];
    const float* ln_g           = (const float*)d_in[11];
    const float* ln_b           = (const float*)d_in[12];
    const float* W_node         = (const float*)d_in[13];
    const float* b_node         = (const float*)d_in[14];
    const float* emb_chg        = (const float*)d_in[15];
    const float* emb_spin       = (const float*)d_in[16];
    const float* W_cs           = (const float*)d_in[17];
    const float* b_cs           = (const float*)d_in[18];
    const float* W_edge         = (const float*)d_in[19];
    const float* b_edge         = (const float*)d_in[20];
    const float* W_ef           = (const float*)d_in[21];
    const float* b_ef           = (const float*)d_in[22];
    float* out = (float*)d_out;

    cudaFuncSetAttribute(node_kernel, cudaFuncAttributeMaxDynamicSharedMemorySize, SMEM_NODE);
    cudaFuncSetAttribute(edge_hmma<192, 0>, cudaFuncAttributeMaxDynamicSharedMemorySize, SMEM_E1);
    cudaFuncSetAttribute(edge_hmma<256, 1>, cudaFuncAttributeMaxDynamicSharedMemorySize, SMEM_E2);

    int nsm = 148;
    cudaDeviceGetAttribute(&nsm, cudaDevAttrMultiProcessorCount, 0);

    cs_kernel<<<NG, HH>>>(charge, spin, emb_chg, emb_spin, W_cs, b_cs);
    node_kernel<<<nsm, 256, SMEM_NODE>>>(atomic_numbers, nde, nbatch, emb_atom,
                                         W_nd, b_nd, ln_g, ln_b, W_node, b_node);
    edge_hmma<192, 0><<<nsm, 256, SMEM_E1>>>(edist, edir, nullptr, W_edge, b_edge, nullptr);
    edge_hmma<256, 1><<<nsm, 256, SMEM_E2>>>(nullptr, nullptr, nsrc, W_ef, b_ef, out);
}

// round 5
// speedup vs baseline: 2.0645x; 1.0345x over previous
#include <cuda_runtime.h>
#include <cuda_bf16.h>
#include <cstdint>
#include <cstddef>

// ---------------- problem constants ----------------
#define NN     50000
#define NE     800000
#define NG     32
#define HH     128
#define NDD    16
#define EDD    128
#define DD2D   64

#define NT_E   (NE/256)     // 3125 edge tiles of 256
#define NT_N   (NN/16)      // 3125 node tiles of 16

// ---------------- scratch (device globals: no allocation allowed) ----------------
__device__ float g_cs[NG * HH];
__device__ float g_node[(size_t)NN * HH];
__device__ float g_eattr[(size_t)NE * HH];

// ---------------- helpers ----------------
__device__ __forceinline__ float gelu_f(float x) {
    return 0.5f * x * (1.0f + erff(x * 0.70710678118654752440f));
}

// pack two f32 -> bf16x2 (lo half = a, hi half = b)
__device__ __forceinline__ uint32_t cvt2(float a, float b) {
    uint32_t r;
    asm("cvt.rn.bf16x2.f32 %0, %1, %2;" : "=r"(r) : "f"(b), "f"(a));
    return r;
}

// split a float2 pair into hi bf16x2 and lo bf16x2
__device__ __forceinline__ void split2(float2 v, uint32_t& hi, uint32_t& lo) {
    hi = cvt2(v.x, v.y);
    float fa = __uint_as_float(hi << 16);
    float fb = __uint_as_float(hi & 0xFFFF0000u);
    lo = cvt2(v.x - fa, v.y - fb);
}

__device__ __forceinline__ void mma_bf16(float c[4], const uint32_t a[4],
                                         uint32_t b0, uint32_t b1) {
    asm volatile("mma.sync.aligned.m16n8k16.row.col.f32.bf16.bf16.f32 "
                 "{%0,%1,%2,%3}, {%4,%5,%6,%7}, {%8,%9}, {%0,%1,%2,%3};"
                 : "+f"(c[0]), "+f"(c[1]), "+f"(c[2]), "+f"(c[3])
                 : "r"(a[0]), "r"(a[1]), "r"(a[2]), "r"(a[3]), "r"(b0), "r"(b1));
}

// ======================================================================
// Kernel 0: cs[g] = gelu(concat(emb_chg[charge], emb_spin[spin]) @ W_cs + b_cs)
// ======================================================================
__global__ void cs_kernel(const int* __restrict__ charge, const int* __restrict__ spin,
                          const float* __restrict__ emb_chg, const float* __restrict__ emb_spin,
                          const float* __restrict__ W_cs, const float* __restrict__ b_cs) {
    __shared__ float xv[2 * HH];
    int g = blockIdx.x, j = threadIdx.x;
    int c = charge[g], s = spin[g];
    xv[j]      = emb_chg[c * HH + j];
    xv[HH + j] = emb_spin[s * HH + j];
    __syncthreads();
    float acc = b_cs[j];
    #pragma unroll 8
    for (int k = 0; k < 2 * HH; k++) acc += xv[k] * W_cs[k * HH + j];
    g_cs[g * HH + j] = gelu_f(acc);
}

// ======================================================================
// Kernel 1: node features (persistent; W_node resident in smem) — fp32 path
// ======================================================================
#define SX_STRIDE 257
#define SMEM_NODE ((32768 + 16 * SX_STRIDE) * 4)

__global__ void __launch_bounds__(256, 1)
node_kernel(const int* __restrict__ an, const float* __restrict__ nde,
            const int* __restrict__ nbatch,
            const float* __restrict__ emb_atom, const float* __restrict__ W_nd,
            const float* __restrict__ b_nd, const float* __restrict__ ln_g,
            const float* __restrict__ ln_b, const float* __restrict__ W_node,
            const float* __restrict__ b_node) {
    extern __shared__ float sm[];
    float* sW = sm;                  // [256][128]
    float* sx = sm + 32768;          // [16][257]
    __shared__ float smu[16], srs[16];
    int tid = threadIdx.x;

    for (int i = tid; i < 32768 / 4; i += 256)
        ((float4*)sW)[i] = ((const float4*)W_node)[i];

    for (int t0 = blockIdx.x; t0 < NT_N; t0 += gridDim.x) {
        __syncthreads();
        int n0 = t0 * 16;
        for (int idx = tid; idx < 16 * HH; idx += 256) {
            int n = idx >> 7, j = idx & 127;
            int node = n0 + n;
            float a = emb_atom[an[node] * HH + j];
            float accv = b_nd[j];
            const float* nrow = nde + node * NDD;
            #pragma unroll
            for (int k = 0; k < NDD; k++) accv += nrow[k] * W_nd[k * HH + j];
            sx[n * SX_STRIDE + j]      = a;
            sx[n * SX_STRIDE + HH + j] = gelu_f(accv);
        }
        __syncthreads();
        int w = tid >> 5, lane = tid & 31;
        for (int n = w; n < 16; n += 8) {
            float s1 = 0.f, s2 = 0.f;
            for (int k = lane; k < 256; k += 32) {
                float v = sx[n * SX_STRIDE + k]; s1 += v; s2 += v * v;
            }
            #pragma unroll
            for (int o = 16; o > 0; o >>= 1) {
                s1 += __shfl_down_sync(0xffffffffu, s1, o);
                s2 += __shfl_down_sync(0xffffffffu, s2, o);
            }
            if (lane == 0) {
                float mu  = s1 * (1.f / 256.f);
                float var = s2 * (1.f / 256.f) - mu * mu;
                smu[n] = mu; srs[n] = rsqrtf(var + 1e-5f);
            }
        }
        __syncthreads();
        for (int idx = tid; idx < 16 * 256; idx += 256) {
            int n = idx >> 8, k = idx & 255;
            sx[n * SX_STRIDE + k] =
                (sx[n * SX_STRIDE + k] - smu[n]) * srs[n] * ln_g[k] + ln_b[k];
        }
        __syncthreads();
        {
            int n = tid >> 4, jb = tid & 15;
            float acc[8];
            #pragma unroll
            for (int q = 0; q < 8; q++) acc[q] = b_node[jb * 8 + q];
            const float* xr = sx + n * SX_STRIDE;
            #pragma unroll 4
            for (int k = 0; k < 256; k++) {
                float a = xr[k];
                const float4 b0 = *(const float4*)&sW[k * HH + jb * 8];
                const float4 b1 = *(const float4*)&sW[k * HH + jb * 8 + 4];
                acc[0] += a * b0.x; acc[1] += a * b0.y; acc[2] += a * b0.z; acc[3] += a * b0.w;
                acc[4] += a * b1.x; acc[5] += a * b1.y; acc[6] += a * b1.z; acc[7] += a * b1.w;
            }
            int node = n0 + n;
            const float* csr = g_cs + nbatch[node] * HH;
            float4 o0, o1;
            o0.x = gelu_f(acc[0]) + csr[jb * 8 + 0];
            o0.y = gelu_f(acc[1]) + csr[jb * 8 + 1];
            o0.z = gelu_f(acc[2]) + csr[jb * 8 + 2];
            o0.w = gelu_f(acc[3]) + csr[jb * 8 + 3];
            o1.x = gelu_f(acc[4]) + csr[jb * 8 + 4];
            o1.y = gelu_f(acc[5]) + csr[jb * 8 + 5];
            o1.z = gelu_f(acc[6]) + csr[jb * 8 + 6];
            o1.w = gelu_f(acc[7]) + csr[jb * 8 + 7];
            *(float4*)&g_node[(size_t)node * HH + jb * 8]     = o0;
            *(float4*)&g_node[(size_t)node * HH + jb * 8 + 4] = o1;
        }
    }
}

// ======================================================================
// Edge GEMMs via warp-level bf16 HMMA, hi/lo 3-pass split.
// Warp tile: 32 rows x 128 cols (tile = 256 edges, 8 warps).
// W in smem in EXACT mma-fragment layout: sf[ks][nb][lane] = {bh0,bh1,bl0,bl1}
//   -> 16 conflict-free LDS.128 per k-step (vs 64 LDS.32 before).
// A: gmem -> registers directly, one k-step prefetch; no syncthreads in loop.
//   MODE 0: eattr = gelu([edist|edir] @ W_edge + b)          K=192
//   MODE 1: out   = gelu([node[src]|eattr] @ W_ef + b)       K=256
// ======================================================================
template<int KDIM, int MODE>
__global__ void __launch_bounds__(256, 1)
edge_hmma(const float* __restrict__ P0, const float* __restrict__ P1,
          const int* __restrict__ srcIdx, const float* __restrict__ W,
          const float* __restrict__ bias, float* __restrict__ outp)
{
    constexpr int NKS = KDIM / 16;         // k-steps

    extern __shared__ uint4 sf[];          // [NKS][16][32]

    float* dst = (MODE == 0) ? g_eattr : outp;

    const int tid = threadIdx.x, lane = tid & 31, wid = tid >> 5;
    const int lr = lane >> 2;              // fragment row 0..7
    const int kc = (lane & 3) * 2;         // fragment k pair base

    // ---- build W fragment table (once per CTA) ----
    for (int idx = tid; idx < NKS * 16 * 32; idx += 256) {
        int li = idx & 31, nb = (idx >> 5) & 15, ks = idx >> 9;
        int n  = nb * 8 + (li >> 2);
        int kg = ks * 16 + (li & 3) * 2;
        float2 w0 = make_float2(W[(size_t)kg * HH + n],       W[(size_t)(kg + 1) * HH + n]);
        float2 w1 = make_float2(W[(size_t)(kg + 8) * HH + n], W[(size_t)(kg + 9) * HH + n]);
        uint32_t h0, l0, h1, l1;
        split2(w0, h0, l0);
        split2(w1, h1, l1);
        sf[idx] = make_uint4(h0, h1, l0, l1);
    }
    __syncthreads();

    const uint4* wfl = sf + lane;

    for (int tile = blockIdx.x; tile < NT_E; tile += gridDim.x) {
        const int e0 = tile * 256;
        const int mbase = e0 + wid * 32 + lr;   // row of v[0]

        // per-row pointers (4 rows: lr, lr+8, lr+16, lr+24), two k-regions each
        const float *pA[4], *pB[4];
        #pragma unroll
        for (int r = 0; r < 4; r++) {
            const int gr = mbase + r * 8;
            if (MODE == 0) {
                pA[r] = P0 + (size_t)gr * EDD + kc;
                pB[r] = P1 + (size_t)gr * DD2D + kc;
            } else {
                pA[r] = g_node + (size_t)srcIdx[gr] * HH + kc;
                pB[r] = g_eattr + (size_t)gr * HH + kc;
            }
        }

        // accumulators: 2 m-frags x 16 n-blocks x 4
        float acc0[16][4], acc1[16][4];
        #pragma unroll
        for (int nb = 0; nb < 16; nb++) {
            float2 b = *(const float2*)(bias + nb * 8 + kc);
            acc0[nb][0] = b.x; acc0[nb][1] = b.y; acc0[nb][2] = b.x; acc0[nb][3] = b.y;
            acc1[nb][0] = b.x; acc1[nb][1] = b.y; acc1[nb][2] = b.x; acc1[nb][3] = b.y;
        }

        // A fragment buffer: v[r][half] (rows lr,lr+8,lr+16,lr+24; k halves 0,8)
        float2 v[4][2];
        #define LOADA(KG)                                                         \
        {                                                                         \
            _Pragma("unroll")                                                     \
            for (int r = 0; r < 4; r++) {                                         \
                const float* q = ((KG) < 128) ? pA[r] + (KG) : pB[r] + ((KG) - 128); \
                v[r][0] = *(const float2*)q;                                      \
                v[r][1] = *(const float2*)(q + 8);                                \
            }                                                                     \
        }

        LOADA(0);

        #pragma unroll
        for (int ks = 0; ks < NKS; ks++) {
            // split current A fragments (frees v), then prefetch next k-step
            uint32_t ah0[4], al0[4], ah1[4], al1[4];
            split2(v[0][0], ah0[0], al0[0]); split2(v[1][0], ah0[1], al0[1]);
            split2(v[0][1], ah0[2], al0[2]); split2(v[1][1], ah0[3], al0[3]);
            split2(v[2][0], ah1[0], al1[0]); split2(v[3][0], ah1[1], al1[1]);
            split2(v[2][1], ah1[2], al1[2]); split2(v[3][1], ah1[3], al1[3]);
            if (ks + 1 < NKS) LOADA(ks * 16 + 16);

            const uint4* wk = wfl + ks * 512;
            #pragma unroll
            for (int h = 0; h < 2; h++) {
                uint4 f[8];
                #pragma unroll
                for (int i = 0; i < 8; i++) f[i] = wk[(h * 8 + i) * 32];
                // pass 1: hi x Whi (16 independent accumulator groups)
                #pragma unroll
                for (int i = 0; i < 8; i++) mma_bf16(acc0[h * 8 + i], ah0, f[i].x, f[i].y);
                #pragma unroll
                for (int i = 0; i < 8; i++) mma_bf16(acc1[h * 8 + i], ah1, f[i].x, f[i].y);
                // pass 2: lo x Whi
                #pragma unroll
                for (int i = 0; i < 8; i++) mma_bf16(acc0[h * 8 + i], al0, f[i].x, f[i].y);
                #pragma unroll
                for (int i = 0; i < 8; i++) mma_bf16(acc1[h * 8 + i], al1, f[i].x, f[i].y);
                // pass 3: hi x Wlo
                #pragma unroll
                for (int i = 0; i < 8; i++) mma_bf16(acc0[h * 8 + i], ah0, f[i].z, f[i].w);
                #pragma unroll
                for (int i = 0; i < 8; i++) mma_bf16(acc1[h * 8 + i], ah1, f[i].z, f[i].w);
            }
        }
        #undef LOADA

        // ---- epilogue: gelu + store ----
        #pragma unroll
        for (int nb = 0; nb < 16; nb++) {
            const int col = nb * 8 + kc;
            float2 o;
            o.x = gelu_f(acc0[nb][0]); o.y = gelu_f(acc0[nb][1]);
            *(float2*)(dst + (size_t)mbase * HH + col) = o;
            o.x = gelu_f(acc0[nb][2]); o.y = gelu_f(acc0[nb][3]);
            *(float2*)(dst + (size_t)(mbase + 8) * HH + col) = o;
            o.x = gelu_f(acc1[nb][0]); o.y = gelu_f(acc1[nb][1]);
            *(float2*)(dst + (size_t)(mbase + 16) * HH + col) = o;
            o.x = gelu_f(acc1[nb][2]); o.y = gelu_f(acc1[nb][3]);
            *(float2*)(dst + (size_t)(mbase + 24) * HH + col) = o;
        }
    }
}

#define SMEM_E1 (12 * 16 * 32 * 16)   //  98,304 B
#define SMEM_E2 (16 * 16 * 32 * 16)   // 131,072 B

// ======================================================================
// launch
// ======================================================================
extern "C" void kernel_launch(void* const* d_in, const int* in_sizes, int n_in,
                              void* d_out, int out_size) {
    const int*   atomic_numbers = (const int*)  d_in[0];
    const float* nde            = (const float*)d_in[1];
    const float* edist          = (const float*)d_in[2];
    const float* edir           = (const float*)d_in[3];
    const int*   charge         = (const int*)  d_in[4];
    const int*   spin           = (const int*)  d_in[5];
    const int*   nbatch         = (const int*)  d_in[6];
    const int*   nsrc           = (const int*)  d_in[7];
    const float* emb_atom       = (const float*)d_in[8];
    const float* W_nd           = (const float*)d_in[9];
    const float* b_nd           = (const float*)d_in[10];
    const float* ln_g           = (const float*)d_in[11];
    const float* ln_b           = (const float*)d_in[12];
    const float* W_node         = (const float*)d_in[13];
    const float* b_node         = (const float*)d_in[14];
    const float* emb_chg        = (const float*)d_in[15];
    const float* emb_spin       = (const float*)d_in[16];
    const float* W_cs           = (const float*)d_in[17];
    const float* b_cs           = (const float*)d_in[18];
    const float* W_edge         = (const float*)d_in[19];
    const float* b_edge         = (const float*)d_in[20];
    const float* W_ef           = (const float*)d_in[21];
    const float* b_ef           = (const float*)d_in[22];
    float* out = (float*)d_out;

    cudaFuncSetAttribute(node_kernel, cudaFuncAttributeMaxDynamicSharedMemorySize, SMEM_NODE);
    cudaFuncSetAttribute(edge_hmma<192, 0>, cudaFuncAttributeMaxDynamicSharedMemorySize, SMEM_E1);
    cudaFuncSetAttribute(edge_hmma<256, 1>, cudaFuncAttributeMaxDynamicSharedMemorySize, SMEM_E2);

    int nsm = 148;
    cudaDeviceGetAttribute(&nsm, cudaDevAttrMultiProcessorCount, 0);

    cs_kernel<<<NG, HH>>>(charge, spin, emb_chg, emb_spin, W_cs, b_cs);
    node_kernel<<<nsm, 256, SMEM_NODE>>>(atomic_numbers, nde, nbatch, emb_atom,
                                         W_nd, b_nd, ln_g, ln_b, W_node, b_node);
    edge_hmma<192, 0><<<nsm, 256, SMEM_E1>>>(edist, edir, nullptr, W_edge, b_edge, nullptr);
    edge_hmma<256, 1><<<nsm, 256, SMEM_E2>>>(nullptr, nullptr, nsrc, W_ef, b_ef, out);
}

// round 6
// speedup vs baseline: 2.1293x; 1.0314x over previous
#include <cuda_runtime.h>
#include <cuda_bf16.h>
#include <cstdint>
#include <cstddef>

// ---------------- problem constants ----------------
#define NN     50000
#define NE     800000
#define NG     32
#define HH     128
#define NDD    16
#define EDD    128
#define DD2D   64

#define NT_E   (NE/128)     // 6250 edge tiles of 128
#define NT_N   (NN/16)      // 3125 node tiles of 16

// ---------------- scratch (device globals: no allocation allowed) ----------------
__device__ float g_cs[NG * HH];
__device__ float g_node[(size_t)NN * HH];
__device__ float g_eattr[(size_t)NE * HH];

// ---------------- helpers ----------------
__device__ __forceinline__ float gelu_f(float x) {
    return 0.5f * x * (1.0f + erff(x * 0.70710678118654752440f));
}

// pack two f32 -> bf16x2 (lo half = a, hi half = b)
__device__ __forceinline__ uint32_t cvt2(float a, float b) {
    uint32_t r;
    asm("cvt.rn.bf16x2.f32 %0, %1, %2;" : "=r"(r) : "f"(b), "f"(a));
    return r;
}

// split a float2 pair into hi bf16x2 and lo bf16x2
__device__ __forceinline__ void split2(float2 v, uint32_t& hi, uint32_t& lo) {
    hi = cvt2(v.x, v.y);
    float fa = __uint_as_float(hi << 16);
    float fb = __uint_as_float(hi & 0xFFFF0000u);
    lo = cvt2(v.x - fa, v.y - fb);
}

__device__ __forceinline__ void mma_bf16(float c[4], const uint32_t a[4],
                                         uint32_t b0, uint32_t b1) {
    asm volatile("mma.sync.aligned.m16n8k16.row.col.f32.bf16.bf16.f32 "
                 "{%0,%1,%2,%3}, {%4,%5,%6,%7}, {%8,%9}, {%0,%1,%2,%3};"
                 : "+f"(c[0]), "+f"(c[1]), "+f"(c[2]), "+f"(c[3])
                 : "r"(a[0]), "r"(a[1]), "r"(a[2]), "r"(a[3]), "r"(b0), "r"(b1));
}

// ======================================================================
// Kernel 0: cs[g] = gelu(concat(emb_chg[charge], emb_spin[spin]) @ W_cs + b_cs)
// ======================================================================
__global__ void cs_kernel(const int* __restrict__ charge, const int* __restrict__ spin,
                          const float* __restrict__ emb_chg, const float* __restrict__ emb_spin,
                          const float* __restrict__ W_cs, const float* __restrict__ b_cs) {
    __shared__ float xv[2 * HH];
    int g = blockIdx.x, j = threadIdx.x;
    int c = charge[g], s = spin[g];
    xv[j]      = emb_chg[c * HH + j];
    xv[HH + j] = emb_spin[s * HH + j];
    __syncthreads();
    float acc = b_cs[j];
    #pragma unroll 8
    for (int k = 0; k < 2 * HH; k++) acc += xv[k] * W_cs[k * HH + j];
    g_cs[g * HH + j] = gelu_f(acc);
}

// ======================================================================
// Kernel 1: node features (persistent; W_node resident in smem) — fp32 path
// ======================================================================
#define SX_STRIDE 257
#define SMEM_NODE ((32768 + 16 * SX_STRIDE) * 4)

__global__ void __launch_bounds__(256, 1)
node_kernel(const int* __restrict__ an, const float* __restrict__ nde,
            const int* __restrict__ nbatch,
            const float* __restrict__ emb_atom, const float* __restrict__ W_nd,
            const float* __restrict__ b_nd, const float* __restrict__ ln_g,
            const float* __restrict__ ln_b, const float* __restrict__ W_node,
            const float* __restrict__ b_node) {
    extern __shared__ float sm[];
    float* sW = sm;                  // [256][128]
    float* sx = sm + 32768;          // [16][257]
    __shared__ float smu[16], srs[16];
    int tid = threadIdx.x;

    for (int i = tid; i < 32768 / 4; i += 256)
        ((float4*)sW)[i] = ((const float4*)W_node)[i];

    for (int t0 = blockIdx.x; t0 < NT_N; t0 += gridDim.x) {
        __syncthreads();
        int n0 = t0 * 16;
        for (int idx = tid; idx < 16 * HH; idx += 256) {
            int n = idx >> 7, j = idx & 127;
            int node = n0 + n;
            float a = emb_atom[an[node] * HH + j];
            float accv = b_nd[j];
            const float* nrow = nde + node * NDD;
            #pragma unroll
            for (int k = 0; k < NDD; k++) accv += nrow[k] * W_nd[k * HH + j];
            sx[n * SX_STRIDE + j]      = a;
            sx[n * SX_STRIDE + HH + j] = gelu_f(accv);
        }
        __syncthreads();
        int w = tid >> 5, lane = tid & 31;
        for (int n = w; n < 16; n += 8) {
            float s1 = 0.f, s2 = 0.f;
            for (int k = lane; k < 256; k += 32) {
                float v = sx[n * SX_STRIDE + k]; s1 += v; s2 += v * v;
            }
            #pragma unroll
            for (int o = 16; o > 0; o >>= 1) {
                s1 += __shfl_down_sync(0xffffffffu, s1, o);
                s2 += __shfl_down_sync(0xffffffffu, s2, o);
            }
            if (lane == 0) {
                float mu  = s1 * (1.f / 256.f);
                float var = s2 * (1.f / 256.f) - mu * mu;
                smu[n] = mu; srs[n] = rsqrtf(var + 1e-5f);
            }
        }
        __syncthreads();
        for (int idx = tid; idx < 16 * 256; idx += 256) {
            int n = idx >> 8, k = idx & 255;
            sx[n * SX_STRIDE + k] =
                (sx[n * SX_STRIDE + k] - smu[n]) * srs[n] * ln_g[k] + ln_b[k];
        }
        __syncthreads();
        {
            int n = tid >> 4, jb = tid & 15;
            float acc[8];
            #pragma unroll
            for (int q = 0; q < 8; q++) acc[q] = b_node[jb * 8 + q];
            const float* xr = sx + n * SX_STRIDE;
            #pragma unroll 4
            for (int k = 0; k < 256; k++) {
                float a = xr[k];
                const float4 b0 = *(const float4*)&sW[k * HH + jb * 8];
                const float4 b1 = *(const float4*)&sW[k * HH + jb * 8 + 4];
                acc[0] += a * b0.x; acc[1] += a * b0.y; acc[2] += a * b0.z; acc[3] += a * b0.w;
                acc[4] += a * b1.x; acc[5] += a * b1.y; acc[6] += a * b1.z; acc[7] += a * b1.w;
            }
            int node = n0 + n;
            const float* csr = g_cs + nbatch[node] * HH;
            float4 o0, o1;
            o0.x = gelu_f(acc[0]) + csr[jb * 8 + 0];
            o0.y = gelu_f(acc[1]) + csr[jb * 8 + 1];
            o0.z = gelu_f(acc[2]) + csr[jb * 8 + 2];
            o0.w = gelu_f(acc[3]) + csr[jb * 8 + 3];
            o1.x = gelu_f(acc[4]) + csr[jb * 8 + 4];
            o1.y = gelu_f(acc[5]) + csr[jb * 8 + 5];
            o1.z = gelu_f(acc[6]) + csr[jb * 8 + 6];
            o1.w = gelu_f(acc[7]) + csr[jb * 8 + 7];
            *(float4*)&g_node[(size_t)node * HH + jb * 8]     = o0;
            *(float4*)&g_node[(size_t)node * HH + jb * 8 + 4] = o1;
        }
    }
}

// ======================================================================
// Edge GEMMs via warp-level bf16 HMMA, hi/lo 3-pass split.
// 512 threads, 16 warps in 8(m) x 2(n); warp tile = 16 rows x 64 cols.
// Tile = 128 edges. W in smem in exact mma-fragment layout (uint4 per lane:
// {bh0,bh1,bl0,bl1}) -> 8 conflict-free LDS.128 per warp per k-step.
// A: gmem -> registers directly, one k-step prefetch; no syncthreads in loop.
//   MODE 0: eattr = gelu([edist|edir] @ W_edge + b)          K=192
//   MODE 1: out   = gelu([node[src]|eattr] @ W_ef + b)       K=256
// ======================================================================
template<int KDIM, int MODE>
__global__ void __launch_bounds__(512, 1)
edge_hmma(const float* __restrict__ P0, const float* __restrict__ P1,
          const int* __restrict__ srcIdx, const float* __restrict__ W,
          const float* __restrict__ bias, float* __restrict__ outp)
{
    constexpr int NKS = KDIM / 16;         // k-steps

    extern __shared__ uint4 sf[];          // [NKS][16][32]

    float* dst = (MODE == 0) ? g_eattr : outp;

    const int tid = threadIdx.x, lane = tid & 31, wid = tid >> 5;
    const int warp_m = wid & 7, warp_n = wid >> 3;
    const int lr = lane >> 2;              // fragment row 0..7
    const int kc = (lane & 3) * 2;         // fragment k pair base

    // ---- build W fragment table (once per CTA) ----
    for (int idx = tid; idx < NKS * 16 * 32; idx += 512) {
        int li = idx & 31, nb = (idx >> 5) & 15, ks = idx >> 9;
        int n  = nb * 8 + (li >> 2);
        int kg = ks * 16 + (li & 3) * 2;
        float2 w0 = make_float2(W[(size_t)kg * HH + n],       W[(size_t)(kg + 1) * HH + n]);
        float2 w1 = make_float2(W[(size_t)(kg + 8) * HH + n], W[(size_t)(kg + 9) * HH + n]);
        uint32_t h0, l0, h1, l1;
        split2(w0, h0, l0);
        split2(w1, h1, l1);
        sf[idx] = make_uint4(h0, h1, l0, l1);
    }
    __syncthreads();

    // this warp's n-half of the fragment table
    const uint4* wfl = sf + (size_t)warp_n * 8 * 32 + lane;

    for (int tile = blockIdx.x; tile < NT_E; tile += gridDim.x) {
        const int e0 = tile * 128;
        const int mbase = e0 + warp_m * 16 + lr;   // row of v[0]

        // per-row pointers (rows mbase, mbase+8), two k-regions each
        const float *pA[2], *pB[2];
        #pragma unroll
        for (int r = 0; r < 2; r++) {
            const int gr = mbase + r * 8;
            if (MODE == 0) {
                pA[r] = P0 + (size_t)gr * EDD + kc;
                pB[r] = P1 + (size_t)gr * DD2D + kc;
            } else {
                pA[r] = g_node + (size_t)srcIdx[gr] * HH + kc;
                pB[r] = g_eattr + (size_t)gr * HH + kc;
            }
        }

        // accumulators: 8 n-blocks x 4 (init with bias)
        float acc[8][4];
        #pragma unroll
        for (int i = 0; i < 8; i++) {
            float2 b = *(const float2*)(bias + (warp_n * 8 + i) * 8 + kc);
            acc[i][0] = b.x; acc[i][1] = b.y; acc[i][2] = b.x; acc[i][3] = b.y;
        }

        // A fragment buffer: v[r][half] (rows lr, lr+8; k halves 0, 8)
        float2 v[2][2];
        #define LOADA(KG)                                                            \
        {                                                                            \
            _Pragma("unroll")                                                        \
            for (int r = 0; r < 2; r++) {                                            \
                const float* q = ((KG) < 128) ? pA[r] + (KG) : pB[r] + ((KG) - 128); \
                v[r][0] = *(const float2*)q;                                         \
                v[r][1] = *(const float2*)(q + 8);                                   \
            }                                                                        \
        }

        LOADA(0);

        #pragma unroll
        for (int ks = 0; ks < NKS; ks++) {
            // split current A fragments (frees v), then prefetch next k-step
            uint32_t ah[4], al[4];
            split2(v[0][0], ah[0], al[0]);
            split2(v[1][0], ah[1], al[1]);
            split2(v[0][1], ah[2], al[2]);
            split2(v[1][1], ah[3], al[3]);
            if (ks + 1 < NKS) LOADA(ks * 16 + 16);

            // load this warp's 8 B fragments (hi+lo packed)
            uint4 f[8];
            const uint4* wk = wfl + ks * 512;
            #pragma unroll
            for (int i = 0; i < 8; i++) f[i] = wk[i * 32];

            // pass 1: hi x Whi — 8 independent accumulators
            #pragma unroll
            for (int i = 0; i < 8; i++) mma_bf16(acc[i], ah, f[i].x, f[i].y);
            // pass 2: lo x Whi
            #pragma unroll
            for (int i = 0; i < 8; i++) mma_bf16(acc[i], al, f[i].x, f[i].y);
            // pass 3: hi x Wlo
            #pragma unroll
            for (int i = 0; i < 8; i++) mma_bf16(acc[i], ah, f[i].z, f[i].w);
        }
        #undef LOADA

        // ---- epilogue: gelu + store (rows mbase, mbase+8) ----
        #pragma unroll
        for (int i = 0; i < 8; i++) {
            const int col = (warp_n * 8 + i) * 8 + kc;
            float2 o0, o1;
            o0.x = gelu_f(acc[i][0]); o0.y = gelu_f(acc[i][1]);
            o1.x = gelu_f(acc[i][2]); o1.y = gelu_f(acc[i][3]);
            *(float2*)(dst + (size_t)mbase * HH + col)       = o0;
            *(float2*)(dst + (size_t)(mbase + 8) * HH + col) = o1;
        }
    }
}

#define SMEM_E1 (12 * 16 * 32 * 16)   //  98,304 B
#define SMEM_E2 (16 * 16 * 32 * 16)   // 131,072 B

// ======================================================================
// launch
// ======================================================================
extern "C" void kernel_launch(void* const* d_in, const int* in_sizes, int n_in,
                              void* d_out, int out_size) {
    const int*   atomic_numbers = (const int*)  d_in[0];
    const float* nde            = (const float*)d_in[1];
    const float* edist          = (const float*)d_in[2];
    const float* edir           = (const float*)d_in[3];
    const int*   charge         = (const int*)  d_in[4];
    const int*   spin           = (const int*)  d_in[5];
    const int*   nbatch         = (const int*)  d_in[6];
    const int*   nsrc           = (const int*)  d_in[7];
    const float* emb_atom       = (const float*)d_in[8];
    const float* W_nd           = (const float*)d_in[9];
    const float* b_nd           = (const float*)d_in[10];
    const float* ln_g           = (const float*)d_in[11];
    const float* ln_b           = (const float*)d_in[12];
    const float* W_node         = (const float*)d_in[13];
    const float* b_node         = (const float*)d_in[14];
    const float* emb_chg        = (const float*)d_in[15];
    const float* emb_spin       = (const float*)d_in[16];
    const float* W_cs           = (const float*)d_in[17];
    const float* b_cs           = (const float*)d_in[18];
    const float* W_edge         = (const float*)d_in[19];
    const float* b_edge         = (const float*)d_in[20];
    const float* W_ef           = (const float*)d_in[21];
    const float* b_ef           = (const float*)d_in[22];
    float* out = (float*)d_out;

    cudaFuncSetAttribute(node_kernel, cudaFuncAttributeMaxDynamicSharedMemorySize, SMEM_NODE);
    cudaFuncSetAttribute(edge_hmma<192, 0>, cudaFuncAttributeMaxDynamicSharedMemorySize, SMEM_E1);
    cudaFuncSetAttribute(edge_hmma<256, 1>, cudaFuncAttributeMaxDynamicSharedMemorySize, SMEM_E2);

    int nsm = 148;
    cudaDeviceGetAttribute(&nsm, cudaDevAttrMultiProcessorCount, 0);

    cs_kernel<<<NG, HH>>>(charge, spin, emb_chg, emb_spin, W_cs, b_cs);
    node_kernel<<<nsm, 256, SMEM_NODE>>>(atomic_numbers, nde, nbatch, emb_atom,
                                         W_nd, b_nd, ln_g, ln_b, W_node, b_node);
    edge_hmma<192, 0><<<nsm, 512, SMEM_E1>>>(edist, edir, nullptr, W_edge, b_edge, nullptr);
    edge_hmma<256, 1><<<nsm, 512, SMEM_E2>>>(nullptr, nullptr, nsrc, W_ef, b_ef, out);
}

// round 7
// speedup vs baseline: 2.6850x; 1.2610x over previous
#include <cuda_runtime.h>
#include <cuda_bf16.h>
#include <cstdint>
#include <cstddef>

// ---------------- problem constants ----------------
#define NN     50000
#define NE     800000
#define NG     32
#define HH     128
#define NDD    16
#define EDD    128
#define DD2D   64

#define NT_E   (NE/128)     // 6250 edge tiles of 128
#define NT_N   (NN/16)      // 3125 node tiles of 16

// ---------------- scratch (device globals: no allocation allowed) ----------------
__device__ float g_cs[NG * HH];
__device__ float g_node[(size_t)NN * HH];
__device__ float g_eattr[(size_t)NE * HH];

// ---------------- helpers ----------------
__device__ __forceinline__ float gelu_f(float x) {
    return 0.5f * x * (1.0f + erff(x * 0.70710678118654752440f));
}

// pack two f32 -> bf16x2 (lo half = a, hi half = b)
__device__ __forceinline__ uint32_t cvt2(float a, float b) {
    uint32_t r;
    asm("cvt.rn.bf16x2.f32 %0, %1, %2;" : "=r"(r) : "f"(b), "f"(a));
    return r;
}

// split a float2 pair into hi bf16x2 and lo bf16x2
__device__ __forceinline__ void split2(float2 v, uint32_t& hi, uint32_t& lo) {
    hi = cvt2(v.x, v.y);
    float fa = __uint_as_float(hi << 16);
    float fb = __uint_as_float(hi & 0xFFFF0000u);
    lo = cvt2(v.x - fa, v.y - fb);
}

__device__ __forceinline__ void mma_bf16(float c[4], const uint32_t a[4],
                                         uint32_t b0, uint32_t b1) {
    asm volatile("mma.sync.aligned.m16n8k16.row.col.f32.bf16.bf16.f32 "
                 "{%0,%1,%2,%3}, {%4,%5,%6,%7}, {%8,%9}, {%0,%1,%2,%3};"
                 : "+f"(c[0]), "+f"(c[1]), "+f"(c[2]), "+f"(c[3])
                 : "r"(a[0]), "r"(a[1]), "r"(a[2]), "r"(a[3]), "r"(b0), "r"(b1));
}

// build a W fragment table: sf[ks][nb][lane] = {bh0,bh1,bl0,bl1}
// W is [KDIM, 128] row-major fp32; table covers all KDIM/16 k-steps x 16 nb.
template<int KDIM>
__device__ __forceinline__ void build_wtable(uint4* sf, const float* __restrict__ W,
                                             int tid, int nthreads) {
    constexpr int NKS = KDIM / 16;
    for (int idx = tid; idx < NKS * 16 * 32; idx += nthreads) {
        int li = idx & 31, nb = (idx >> 5) & 15, ks = idx >> 9;
        int n  = nb * 8 + (li >> 2);
        int kg = ks * 16 + (li & 3) * 2;
        float2 w0 = make_float2(W[(size_t)kg * HH + n],       W[(size_t)(kg + 1) * HH + n]);
        float2 w1 = make_float2(W[(size_t)(kg + 8) * HH + n], W[(size_t)(kg + 9) * HH + n]);
        uint32_t h0, l0, h1, l1;
        split2(w0, h0, l0);
        split2(w1, h1, l1);
        sf[idx] = make_uint4(h0, h1, l0, l1);
    }
}

// ======================================================================
// Kernel 0: cs[g] = gelu(concat(emb_chg[charge], emb_spin[spin]) @ W_cs + b_cs)
// ======================================================================
__global__ void cs_kernel(const int* __restrict__ charge, const int* __restrict__ spin,
                          const float* __restrict__ emb_chg, const float* __restrict__ emb_spin,
                          const float* __restrict__ W_cs, const float* __restrict__ b_cs) {
    __shared__ float xv[2 * HH];
    int g = blockIdx.x, j = threadIdx.x;
    int c = charge[g], s = spin[g];
    xv[j]      = emb_chg[c * HH + j];
    xv[HH + j] = emb_spin[s * HH + j];
    __syncthreads();
    float acc = b_cs[j];
    #pragma unroll 8
    for (int k = 0; k < 2 * HH; k++) acc += xv[k] * W_cs[k * HH + j];
    g_cs[g * HH + j] = gelu_f(acc);
}

// ======================================================================
// Kernel 1: node features — embed/LN fp32, GEMM via HMMA hi/lo 3-pass.
// smem: W_node fragment table (131072B) + sx[16][264] fp32
// ======================================================================
#define SXS 264
#define SMEM_NODE (131072 + 16 * SXS * 4)

__global__ void __launch_bounds__(256, 1)
node_kernel(const int* __restrict__ an, const float* __restrict__ nde,
            const int* __restrict__ nbatch,
            const float* __restrict__ emb_atom, const float* __restrict__ W_nd,
            const float* __restrict__ b_nd, const float* __restrict__ ln_g,
            const float* __restrict__ ln_b, const float* __restrict__ W_node,
            const float* __restrict__ b_node) {
    extern __shared__ char dyn_smem[];
    uint4* sfW = (uint4*)dyn_smem;               // [16][16][32]
    float* sx  = (float*)(dyn_smem + 131072);    // [16][SXS]
    __shared__ float smu[16], srs[16];
    const int tid = threadIdx.x, lane = tid & 31, wid = tid >> 5;
    const int lr = lane >> 2, kc = (lane & 3) * 2;

    build_wtable<256>(sfW, W_node, tid, 256);
    __syncthreads();

    for (int t0 = blockIdx.x; t0 < NT_N; t0 += gridDim.x) {
        __syncthreads();   // sx reuse fence
        int n0 = t0 * 16;
        // build x[16][256]
        for (int idx = tid; idx < 16 * HH; idx += 256) {
            int n = idx >> 7, j = idx & 127;
            int node = n0 + n;
            float a = emb_atom[an[node] * HH + j];
            float accv = b_nd[j];
            const float* nrow = nde + node * NDD;
            #pragma unroll
            for (int k = 0; k < NDD; k++) accv += nrow[k] * W_nd[k * HH + j];
            sx[n * SXS + j]      = a;
            sx[n * SXS + HH + j] = gelu_f(accv);
        }
        __syncthreads();
        // layernorm stats
        for (int n = wid; n < 16; n += 8) {
            float s1 = 0.f, s2 = 0.f;
            for (int k = lane; k < 256; k += 32) {
                float v = sx[n * SXS + k]; s1 += v; s2 += v * v;
            }
            #pragma unroll
            for (int o = 16; o > 0; o >>= 1) {
                s1 += __shfl_down_sync(0xffffffffu, s1, o);
                s2 += __shfl_down_sync(0xffffffffu, s2, o);
            }
            if (lane == 0) {
                float mu  = s1 * (1.f / 256.f);
                float var = s2 * (1.f / 256.f) - mu * mu;
                smu[n] = mu; srs[n] = rsqrtf(var + 1e-5f);
            }
        }
        __syncthreads();
        for (int idx = tid; idx < 16 * 256; idx += 256) {
            int n = idx >> 8, k = idx & 255;
            sx[n * SXS + k] =
                (sx[n * SXS + k] - smu[n]) * srs[n] * ln_g[k] + ln_b[k];
        }
        __syncthreads();
        // ---- GEMM [16,256]@[256,128] via HMMA; warp handles nb = 2*wid, 2*wid+1
        {
            float acc[2][4];
            #pragma unroll
            for (int i = 0; i < 2; i++) {
                float2 b = *(const float2*)(b_node + (wid * 2 + i) * 8 + kc);
                acc[i][0] = b.x; acc[i][1] = b.y; acc[i][2] = b.x; acc[i][3] = b.y;
            }
            #pragma unroll
            for (int ks = 0; ks < 16; ks++) {
                const float* x0 = sx + lr * SXS + ks * 16 + kc;
                const float* x1 = x0 + 8 * SXS;
                uint32_t ah[4], al[4];
                split2(*(const float2*)x0,       ah[0], al[0]);
                split2(*(const float2*)x1,       ah[1], al[1]);
                split2(*(const float2*)(x0 + 8), ah[2], al[2]);
                split2(*(const float2*)(x1 + 8), ah[3], al[3]);
                uint4 f0 = sfW[ks * 512 + (wid * 2 + 0) * 32 + lane];
                uint4 f1 = sfW[ks * 512 + (wid * 2 + 1) * 32 + lane];
                mma_bf16(acc[0], ah, f0.x, f0.y);
                mma_bf16(acc[1], ah, f1.x, f1.y);
                mma_bf16(acc[0], al, f0.x, f0.y);
                mma_bf16(acc[1], al, f1.x, f1.y);
                mma_bf16(acc[0], ah, f0.z, f0.w);
                mma_bf16(acc[1], ah, f1.z, f1.w);
            }
            // epilogue: gelu + cs add
            const int node0 = n0 + lr, node1 = node0 + 8;
            const float* cs0 = g_cs + nbatch[node0] * HH;
            const float* cs1 = g_cs + nbatch[node1] * HH;
            #pragma unroll
            for (int i = 0; i < 2; i++) {
                const int col = (wid * 2 + i) * 8 + kc;
                float2 o;
                o.x = gelu_f(acc[i][0]) + cs0[col];
                o.y = gelu_f(acc[i][1]) + cs0[col + 1];
                *(float2*)&g_node[(size_t)node0 * HH + col] = o;
                o.x = gelu_f(acc[i][2]) + cs1[col];
                o.y = gelu_f(acc[i][3]) + cs1[col + 1];
                *(float2*)&g_node[(size_t)node1 * HH + col] = o;
            }
        }
    }
}

// ======================================================================
// Edge GEMMs via warp-level bf16 HMMA, hi/lo 3-pass split.
// 256 threads, 8 warps in 4(m) x 2(n); warp tile = 32 rows x 64 cols
// (2 m-fragments share each W fragment load -> W LDS per MMA halved).
// Tile = 128 edges. A: gmem -> registers, one k-step prefetch.
// No __syncthreads in the main loop.
//   MODE 0: eattr = gelu([edist|edir] @ W_edge + b)          K=192
//   MODE 1: out   = gelu([node[src]|eattr] @ W_ef + b)       K=256
// ======================================================================
template<int KDIM, int MODE>
__global__ void __launch_bounds__(256, 1)
edge_hmma(const float* __restrict__ P0, const float* __restrict__ P1,
          const int* __restrict__ srcIdx, const float* __restrict__ W,
          const float* __restrict__ bias, float* __restrict__ outp)
{
    constexpr int NKS = KDIM / 16;         // k-steps

    extern __shared__ char dyn_smem[];
    uint4* sf = (uint4*)dyn_smem;          // [NKS][16][32]

    float* dst = (MODE == 0) ? g_eattr : outp;

    const int tid = threadIdx.x, lane = tid & 31, wid = tid >> 5;
    const int warp_m = wid & 3, warp_n = wid >> 2;
    const int lr = lane >> 2;              // fragment row 0..7
    const int kc = (lane & 3) * 2;         // fragment k pair base

    build_wtable<KDIM>(sf, W, tid, 256);
    __syncthreads();

    // this warp's n-half of the fragment table
    const uint4* wfl = sf + (size_t)warp_n * 8 * 32 + lane;

    for (int tile = blockIdx.x; tile < NT_E; tile += gridDim.x) {
        const int e0 = tile * 128;
        const int mb0 = e0 + warp_m * 32 + lr;   // rows: mb0, +8, +16, +24

        // per-row pointers (4 rows), two k-regions each
        const float *pA[4], *pB[4];
        #pragma unroll
        for (int r = 0; r < 4; r++) {
            const int gr = mb0 + r * 8;
            if (MODE == 0) {
                pA[r] = P0 + (size_t)gr * EDD + kc;
                pB[r] = P1 + (size_t)gr * DD2D + kc;
            } else {
                pA[r] = g_node + (size_t)srcIdx[gr] * HH + kc;
                pB[r] = g_eattr + (size_t)gr * HH + kc;
            }
        }

        // accumulators: 2 m-frags x 8 n-blocks x 4 (init with bias)
        float acc[2][8][4];
        #pragma unroll
        for (int i = 0; i < 8; i++) {
            float2 b = *(const float2*)(bias + (warp_n * 8 + i) * 8 + kc);
            #pragma unroll
            for (int mf = 0; mf < 2; mf++) {
                acc[mf][i][0] = b.x; acc[mf][i][1] = b.y;
                acc[mf][i][2] = b.x; acc[mf][i][3] = b.y;
            }
        }

        // A fragment buffer: v[r][half] (rows mb0+8r; k halves 0, 8)
        float2 v[4][2];
        #define LOADA(KG)                                                            \
        {                                                                            \
            _Pragma("unroll")                                                        \
            for (int r = 0; r < 4; r++) {                                            \
                const float* q = ((KG) < 128) ? pA[r] + (KG) : pB[r] + ((KG) - 128); \
                v[r][0] = *(const float2*)q;                                         \
                v[r][1] = *(const float2*)(q + 8);                                   \
            }                                                                        \
        }

        LOADA(0);

        #pragma unroll
        for (int ks = 0; ks < NKS; ks++) {
            // split current A fragments, then prefetch next k-step
            uint32_t ah0[4], al0[4], ah1[4], al1[4];
            split2(v[0][0], ah0[0], al0[0]);
            split2(v[1][0], ah0[1], al0[1]);
            split2(v[0][1], ah0[2], al0[2]);
            split2(v[1][1], ah0[3], al0[3]);
            split2(v[2][0], ah1[0], al1[0]);
            split2(v[3][0], ah1[1], al1[1]);
            split2(v[2][1], ah1[2], al1[2]);
            split2(v[3][1], ah1[3], al1[3]);
            if (ks + 1 < NKS) LOADA(ks * 16 + 16);

            // this warp's 8 B fragments (hi+lo packed), shared by both m-frags
            uint4 f[8];
            const uint4* wk = wfl + ks * 512;
            #pragma unroll
            for (int i = 0; i < 8; i++) f[i] = wk[i * 32];

            // 6 passes of 8 independent MMAs (48 MMAs per f load)
            #pragma unroll
            for (int i = 0; i < 8; i++) mma_bf16(acc[0][i], ah0, f[i].x, f[i].y);
            #pragma unroll
            for (int i = 0; i < 8; i++) mma_bf16(acc[1][i], ah1, f[i].x, f[i].y);
            #pragma unroll
            for (int i = 0; i < 8; i++) mma_bf16(acc[0][i], al0, f[i].x, f[i].y);
            #pragma unroll
            for (int i = 0; i < 8; i++) mma_bf16(acc[1][i], al1, f[i].x, f[i].y);
            #pragma unroll
            for (int i = 0; i < 8; i++) mma_bf16(acc[0][i], ah0, f[i].z, f[i].w);
            #pragma unroll
            for (int i = 0; i < 8; i++) mma_bf16(acc[1][i], ah1, f[i].z, f[i].w);
        }
        #undef LOADA

        // ---- epilogue: gelu + store ----
        #pragma unroll
        for (int mf = 0; mf < 2; mf++) {
            const int ra = mb0 + mf * 16;
            #pragma unroll
            for (int i = 0; i < 8; i++) {
                const int col = (warp_n * 8 + i) * 8 + kc;
                float2 o0, o1;
                o0.x = gelu_f(acc[mf][i][0]); o0.y = gelu_f(acc[mf][i][1]);
                o1.x = gelu_f(acc[mf][i][2]); o1.y = gelu_f(acc[mf][i][3]);
                *(float2*)(dst + (size_t)ra * HH + col)       = o0;
                *(float2*)(dst + (size_t)(ra + 8) * HH + col) = o1;
            }
        }
    }
}

#define SMEM_E1 (12 * 16 * 32 * 16)   //  98,304 B
#define SMEM_E2 (16 * 16 * 32 * 16)   // 131,072 B

// ======================================================================
// launch
// ======================================================================
extern "C" void kernel_launch(void* const* d_in, const int* in_sizes, int n_in,
                              void* d_out, int out_size) {
    const int*   atomic_numbers = (const int*)  d_in[0];
    const float* nde            = (const float*)d_in[1];
    const float* edist          = (const float*)d_in[2];
    const float* edir           = (const float*)d_in[3];
    const int*   charge         = (const int*)  d_in[4];
    const int*   spin           = (const int*)  d_in[5];
    const int*   nbatch         = (const int*)  d_in[6];
    const int*   nsrc           = (const int*)  d_in[7];
    const float* emb_atom       = (const float*)d_in[8];
    const float* W_nd           = (const float*)d_in[9];
    const float* b_nd           = (const float*)d_in[10];
    const float* ln_g           = (const float*)d_in[11];
    const float* ln_b           = (const float*)d_in[12];
    const float* W_node         = (const float*)d_in[13];
    const float* b_node         = (const float*)d_in[14];
    const float* emb_chg        = (const float*)d_in[15];
    const float* emb_spin       = (const float*)d_in[16];
    const float* W_cs           = (const float*)d_in[17];
    const float* b_cs           = (const float*)d_in[18];
    const float* W_edge         = (const float*)d_in[19];
    const float* b_edge         = (const float*)d_in[20];
    const float* W_ef           = (const float*)d_in[21];
    const float* b_ef           = (const float*)d_in[22];
    float* out = (float*)d_out;

    cudaFuncSetAttribute(node_kernel, cudaFuncAttributeMaxDynamicSharedMemorySize, SMEM_NODE);
    cudaFuncSetAttribute(edge_hmma<192, 0>, cudaFuncAttributeMaxDynamicSharedMemorySize, SMEM_E1);
    cudaFuncSetAttribute(edge_hmma<256, 1>, cudaFuncAttributeMaxDynamicSharedMemorySize, SMEM_E2);

    int nsm = 148;
    cudaDeviceGetAttribute(&nsm, cudaDevAttrMultiProcessorCount, 0);

    cs_kernel<<<NG, HH>>>(charge, spin, emb_chg, emb_spin, W_cs, b_cs);
    node_kernel<<<nsm, 256, SMEM_NODE>>>(atomic_numbers, nde, nbatch, emb_atom,
                                         W_nd, b_nd, ln_g, ln_b, W_node, b_node);
    edge_hmma<192, 0><<<nsm, 256, SMEM_E1>>>(edist, edir, nullptr, W_edge, b_edge, nullptr);
    edge_hmma<256, 1><<<nsm, 256, SMEM_E2>>>(nullptr, nullptr, nsrc, W_ef, b_ef, out);
}

// round 8
// speedup vs baseline: 2.7009x; 1.0059x over previous
#include <cuda_runtime.h>
#include <cuda_bf16.h>
#include <cstdint>
#include <cstddef>

// ---------------- problem constants ----------------
#define NN     50000
#define NE     800000
#define NG     32
#define HH     128
#define NDD    16
#define EDD    128
#define DD2D   64

#define NT_E   (NE/256)     // 3125 edge tiles of 256
#define NT_N   (NN/16)      // 3125 node tiles of 16

// ---------------- scratch (device globals: no allocation allowed) ----------------
__device__ float g_cs[NG * HH];
__device__ float g_node[(size_t)NN * HH];
__device__ float g_eattr[(size_t)NE * HH];

// ---------------- helpers ----------------
__device__ __forceinline__ float gelu_f(float x) {
    return 0.5f * x * (1.0f + erff(x * 0.70710678118654752440f));
}

// pack two f32 -> bf16x2 (lo half = a, hi half = b)
__device__ __forceinline__ uint32_t cvt2(float a, float b) {
    uint32_t r;
    asm("cvt.rn.bf16x2.f32 %0, %1, %2;" : "=r"(r) : "f"(b), "f"(a));
    return r;
}

// split a float2 pair into hi bf16x2 and lo bf16x2
__device__ __forceinline__ void split2(float2 v, uint32_t& hi, uint32_t& lo) {
    hi = cvt2(v.x, v.y);
    float fa = __uint_as_float(hi << 16);
    float fb = __uint_as_float(hi & 0xFFFF0000u);
    lo = cvt2(v.x - fa, v.y - fb);
}

__device__ __forceinline__ void mma_bf16(float c[4], const uint32_t a[4],
                                         uint32_t b0, uint32_t b1) {
    asm volatile("mma.sync.aligned.m16n8k16.row.col.f32.bf16.bf16.f32 "
                 "{%0,%1,%2,%3}, {%4,%5,%6,%7}, {%8,%9}, {%0,%1,%2,%3};"
                 : "+f"(c[0]), "+f"(c[1]), "+f"(c[2]), "+f"(c[3])
                 : "r"(a[0]), "r"(a[1]), "r"(a[2]), "r"(a[3]), "r"(b0), "r"(b1));
}

// build a W fragment table: sf[ks][nb][lane] = {bh0,bh1,bl0,bl1}
template<int KDIM>
__device__ __forceinline__ void build_wtable(uint4* sf, const float* __restrict__ W,
                                             int tid, int nthreads) {
    constexpr int NKS = KDIM / 16;
    for (int idx = tid; idx < NKS * 16 * 32; idx += nthreads) {
        int li = idx & 31, nb = (idx >> 5) & 15, ks = idx >> 9;
        int n  = nb * 8 + (li >> 2);
        int kg = ks * 16 + (li & 3) * 2;
        float2 w0 = make_float2(W[(size_t)kg * HH + n],       W[(size_t)(kg + 1) * HH + n]);
        float2 w1 = make_float2(W[(size_t)(kg + 8) * HH + n], W[(size_t)(kg + 9) * HH + n]);
        uint32_t h0, l0, h1, l1;
        split2(w0, h0, l0);
        split2(w1, h1, l1);
        sf[idx] = make_uint4(h0, h1, l0, l1);
    }
}

// ======================================================================
// Kernel 0: cs[g] = gelu(concat(emb_chg[charge], emb_spin[spin]) @ W_cs + b_cs)
// ======================================================================
__global__ void cs_kernel(const int* __restrict__ charge, const int* __restrict__ spin,
                          const float* __restrict__ emb_chg, const float* __restrict__ emb_spin,
                          const float* __restrict__ W_cs, const float* __restrict__ b_cs) {
    __shared__ float xv[2 * HH];
    int g = blockIdx.x, j = threadIdx.x;
    int c = charge[g], s = spin[g];
    xv[j]      = emb_chg[c * HH + j];
    xv[HH + j] = emb_spin[s * HH + j];
    __syncthreads();
    float acc = b_cs[j];
    #pragma unroll 8
    for (int k = 0; k < 2 * HH; k++) acc += xv[k] * W_cs[k * HH + j];
    g_cs[g * HH + j] = gelu_f(acc);
}

// ======================================================================
// Kernel 1: node features — embed/LN fp32, GEMM via HMMA hi/lo 3-pass.
// smem: W_node fragment table (131072B) + sx[16][264] fp32
// ======================================================================
#define SXS 264
#define SMEM_NODE (131072 + 16 * SXS * 4)

__global__ void __launch_bounds__(256, 1)
node_kernel(const int* __restrict__ an, const float* __restrict__ nde,
            const int* __restrict__ nbatch,
            const float* __restrict__ emb_atom, const float* __restrict__ W_nd,
            const float* __restrict__ b_nd, const float* __restrict__ ln_g,
            const float* __restrict__ ln_b, const float* __restrict__ W_node,
            const float* __restrict__ b_node) {
    extern __shared__ char dyn_smem[];
    uint4* sfW = (uint4*)dyn_smem;               // [16][16][32]
    float* sx  = (float*)(dyn_smem + 131072);    // [16][SXS]
    __shared__ float smu[16], srs[16];
    const int tid = threadIdx.x, lane = tid & 31, wid = tid >> 5;
    const int lr = lane >> 2, kc = (lane & 3) * 2;

    build_wtable<256>(sfW, W_node, tid, 256);
    __syncthreads();

    for (int t0 = blockIdx.x; t0 < NT_N; t0 += gridDim.x) {
        __syncthreads();   // sx reuse fence
        int n0 = t0 * 16;
        for (int idx = tid; idx < 16 * HH; idx += 256) {
            int n = idx >> 7, j = idx & 127;
            int node = n0 + n;
            float a = emb_atom[an[node] * HH + j];
            float accv = b_nd[j];
            const float* nrow = nde + node * NDD;
            #pragma unroll
            for (int k = 0; k < NDD; k++) accv += nrow[k] * W_nd[k * HH + j];
            sx[n * SXS + j]      = a;
            sx[n * SXS + HH + j] = gelu_f(accv);
        }
        __syncthreads();
        for (int n = wid; n < 16; n += 8) {
            float s1 = 0.f, s2 = 0.f;
            for (int k = lane; k < 256; k += 32) {
                float v = sx[n * SXS + k]; s1 += v; s2 += v * v;
            }
            #pragma unroll
            for (int o = 16; o > 0; o >>= 1) {
                s1 += __shfl_down_sync(0xffffffffu, s1, o);
                s2 += __shfl_down_sync(0xffffffffu, s2, o);
            }
            if (lane == 0) {
                float mu  = s1 * (1.f / 256.f);
                float var = s2 * (1.f / 256.f) - mu * mu;
                smu[n] = mu; srs[n] = rsqrtf(var + 1e-5f);
            }
        }
        __syncthreads();
        for (int idx = tid; idx < 16 * 256; idx += 256) {
            int n = idx >> 8, k = idx & 255;
            sx[n * SXS + k] =
                (sx[n * SXS + k] - smu[n]) * srs[n] * ln_g[k] + ln_b[k];
        }
        __syncthreads();
        // ---- GEMM [16,256]@[256,128] via HMMA; warp handles nb = 2*wid, 2*wid+1
        {
            float acc[2][4];
            #pragma unroll
            for (int i = 0; i < 2; i++) {
                float2 b = *(const float2*)(b_node + (wid * 2 + i) * 8 + kc);
                acc[i][0] = b.x; acc[i][1] = b.y; acc[i][2] = b.x; acc[i][3] = b.y;
            }
            #pragma unroll
            for (int ks = 0; ks < 16; ks++) {
                const float* x0 = sx + lr * SXS + ks * 16 + kc;
                const float* x1 = x0 + 8 * SXS;
                uint32_t ah[4], al[4];
                split2(*(const float2*)x0,       ah[0], al[0]);
                split2(*(const float2*)x1,       ah[1], al[1]);
                split2(*(const float2*)(x0 + 8), ah[2], al[2]);
                split2(*(const float2*)(x1 + 8), ah[3], al[3]);
                uint4 f0 = sfW[ks * 512 + (wid * 2 + 0) * 32 + lane];
                uint4 f1 = sfW[ks * 512 + (wid * 2 + 1) * 32 + lane];
                mma_bf16(acc[0], ah, f0.x, f0.y);
                mma_bf16(acc[1], ah, f1.x, f1.y);
                mma_bf16(acc[0], al, f0.x, f0.y);
                mma_bf16(acc[1], al, f1.x, f1.y);
                mma_bf16(acc[0], ah, f0.z, f0.w);
                mma_bf16(acc[1], ah, f1.z, f1.w);
            }
            const int node0 = n0 + lr, node1 = node0 + 8;
            const float* cs0 = g_cs + nbatch[node0] * HH;
            const float* cs1 = g_cs + nbatch[node1] * HH;
            #pragma unroll
            for (int i = 0; i < 2; i++) {
                const int col = (wid * 2 + i) * 8 + kc;
                float2 o;
                o.x = gelu_f(acc[i][0]) + cs0[col];
                o.y = gelu_f(acc[i][1]) + cs0[col + 1];
                *(float2*)&g_node[(size_t)node0 * HH + col] = o;
                o.x = gelu_f(acc[i][2]) + cs1[col];
                o.y = gelu_f(acc[i][3]) + cs1[col + 1];
                *(float2*)&g_node[(size_t)node1 * HH + col] = o;
            }
        }
    }
}

// ======================================================================
// Edge GEMMs via warp-level bf16 HMMA, hi/lo 3-pass split.
// 512 threads, 16 warps in 8(m) x 2(n); warp tile = 32 rows x 64 cols.
// Tile = 256 edges. 2 m-fragments amortize each W fragment load; W fragments
// streamed in chunks of 4 (16 regs) to stay under the 128-reg cap.
// Row pointers held as u32 byte-offsets off uniform bases.
// No __syncthreads in the main loop.
//   MODE 0: eattr = gelu([edist|edir] @ W_edge + b)          K=192
//   MODE 1: out   = gelu([node[src]|eattr] @ W_ef + b)       K=256
// ======================================================================
template<int KDIM, int MODE>
__global__ void __launch_bounds__(512, 1)
edge_hmma(const float* __restrict__ P0, const float* __restrict__ P1,
          const int* __restrict__ srcIdx, const float* __restrict__ W,
          const float* __restrict__ bias, float* __restrict__ outp)
{
    constexpr int NKS = KDIM / 16;         // k-steps

    extern __shared__ char dyn_smem[];
    uint4* sf = (uint4*)dyn_smem;          // [NKS][16][32]

    float* dst = (MODE == 0) ? g_eattr : outp;

    const int tid = threadIdx.x, lane = tid & 31, wid = tid >> 5;
    const int warp_m = wid & 7, warp_n = wid >> 3;
    const int lr = lane >> 2;              // fragment row 0..7
    const int kc = (lane & 3) * 2;         // fragment k pair base

    build_wtable<KDIM>(sf, W, tid, 512);
    __syncthreads();

    // this warp's n-half of the fragment table
    const uint4* wfl = sf + (size_t)warp_n * 8 * 32 + lane;

    // uniform base pointers for the two k-regions
    const char* baseA = (MODE == 0) ? (const char*)P0 : (const char*)g_node;
    const char* baseB = (MODE == 0) ? (const char*)P1 : (const char*)g_eattr;

    for (int tile = blockIdx.x; tile < NT_E; tile += gridDim.x) {
        const int e0 = tile * 256;
        const int mb0 = e0 + warp_m * 32 + lr;   // rows: mb0, +8, +16, +24

        // u32 byte offsets for 4 rows, two k-regions
        uint32_t offA[4], offB[4];
        #pragma unroll
        for (int r = 0; r < 4; r++) {
            const int gr = mb0 + r * 8;
            if (MODE == 0) {
                offA[r] = (uint32_t)gr * (EDD * 4)  + kc * 4;
                offB[r] = (uint32_t)gr * (DD2D * 4) + kc * 4;
            } else {
                offA[r] = (uint32_t)srcIdx[gr] * (HH * 4) + kc * 4;
                offB[r] = (uint32_t)gr * (HH * 4) + kc * 4;
            }
        }

        // accumulators: 2 m-frags x 8 n-blocks x 4 (init with bias)
        float acc[2][8][4];
        #pragma unroll
        for (int i = 0; i < 8; i++) {
            float2 b = *(const float2*)(bias + (warp_n * 8 + i) * 8 + kc);
            #pragma unroll
            for (int mf = 0; mf < 2; mf++) {
                acc[mf][i][0] = b.x; acc[mf][i][1] = b.y;
                acc[mf][i][2] = b.x; acc[mf][i][3] = b.y;
            }
        }

        // A fragment buffer: v[r][half] (rows mb0+8r; k halves 0, 8)
        float2 v[4][2];
        #define LOADA(KG)                                                              \
        {                                                                              \
            _Pragma("unroll")                                                          \
            for (int r = 0; r < 4; r++) {                                              \
                const float* q = ((KG) < 128)                                          \
                    ? (const float*)(baseA + offA[r]) + (KG)                           \
                    : (const float*)(baseB + offB[r]) + ((KG) - 128);                  \
                v[r][0] = *(const float2*)q;                                           \
                v[r][1] = *(const float2*)(q + 8);                                     \
            }                                                                          \
        }

        LOADA(0);

        #pragma unroll
        for (int ks = 0; ks < NKS; ks++) {
            // split current A fragments (frees v), then prefetch next k-step
            uint32_t ah0[4], al0[4], ah1[4], al1[4];
            split2(v[0][0], ah0[0], al0[0]);
            split2(v[1][0], ah0[1], al0[1]);
            split2(v[0][1], ah0[2], al0[2]);
            split2(v[1][1], ah0[3], al0[3]);
            split2(v[2][0], ah1[0], al1[0]);
            split2(v[3][0], ah1[1], al1[1]);
            split2(v[2][1], ah1[2], al1[2]);
            split2(v[3][1], ah1[3], al1[3]);
            if (ks + 1 < NKS) LOADA(ks * 16 + 16);

            const uint4* wk = wfl + ks * 512;
            // two chunks of 4 W fragments; each chunk feeds 24 MMAs
            #pragma unroll
            for (int h = 0; h < 2; h++) {
                uint4 f[4];
                #pragma unroll
                for (int i = 0; i < 4; i++) f[i] = wk[(h * 4 + i) * 32];
                #pragma unroll
                for (int i = 0; i < 4; i++) mma_bf16(acc[0][h * 4 + i], ah0, f[i].x, f[i].y);
                #pragma unroll
                for (int i = 0; i < 4; i++) mma_bf16(acc[1][h * 4 + i], ah1, f[i].x, f[i].y);
                #pragma unroll
                for (int i = 0; i < 4; i++) mma_bf16(acc[0][h * 4 + i], al0, f[i].x, f[i].y);
                #pragma unroll
                for (int i = 0; i < 4; i++) mma_bf16(acc[1][h * 4 + i], al1, f[i].x, f[i].y);
                #pragma unroll
                for (int i = 0; i < 4; i++) mma_bf16(acc[0][h * 4 + i], ah0, f[i].z, f[i].w);
                #pragma unroll
                for (int i = 0; i < 4; i++) mma_bf16(acc[1][h * 4 + i], ah1, f[i].z, f[i].w);
            }
        }
        #undef LOADA

        // ---- epilogue: gelu + store ----
        #pragma unroll
        for (int mf = 0; mf < 2; mf++) {
            const int ra = mb0 + mf * 16;
            #pragma unroll
            for (int i = 0; i < 8; i++) {
                const int col = (warp_n * 8 + i) * 8 + kc;
                float2 o0, o1;
                o0.x = gelu_f(acc[mf][i][0]); o0.y = gelu_f(acc[mf][i][1]);
                o1.x = gelu_f(acc[mf][i][2]); o1.y = gelu_f(acc[mf][i][3]);
                *(float2*)(dst + (size_t)ra * HH + col)       = o0;
                *(float2*)(dst + (size_t)(ra + 8) * HH + col) = o1;
            }
        }
    }
}

#define SMEM_E1 (12 * 16 * 32 * 16)   //  98,304 B
#define SMEM_E2 (16 * 16 * 32 * 16)   // 131,072 B

// ======================================================================
// launch
// ======================================================================
extern "C" void kernel_launch(void* const* d_in, const int* in_sizes, int n_in,
                              void* d_out, int out_size) {
    const int*   atomic_numbers = (const int*)  d_in[0];
    const float* nde            = (const float*)d_in[1];
    const float* edist          = (const float*)d_in[2];
    const float* edir           = (const float*)d_in[3];
    const int*   charge         = (const int*)  d_in[4];
    const int*   spin           = (const int*)  d_in[5];
    const int*   nbatch         = (const int*)  d_in[6];
    const int*   nsrc           = (const int*)  d_in[7];
    const float* emb_atom       = (const float*)d_in[8];
    const float* W_nd           = (const float*)d_in[9];
    const float* b_nd           = (const float*)d_in[10];
    const float* ln_g           = (const float*)d_in[11];
    const float* ln_b           = (const float*)d_in[12];
    const float* W_node         = (const float*)d_in[13];
    const float* b_node         = (const float*)d_in[14];
    const float* emb_chg        = (const float*)d_in[15];
    const float* emb_spin       = (const float*)d_in[16];
    const float* W_cs           = (const float*)d_in[17];
    const float* b_cs           = (const float*)d_in[18];
    const float* W_edge         = (const float*)d_in[19];
    const float* b_edge         = (const float*)d_in[20];
    const float* W_ef           = (const float*)d_in[21];
    const float* b_ef           = (const float*)d_in[22];
    float* out = (float*)d_out;

    cudaFuncSetAttribute(node_kernel, cudaFuncAttributeMaxDynamicSharedMemorySize, SMEM_NODE);
    cudaFuncSetAttribute(edge_hmma<192, 0>, cudaFuncAttributeMaxDynamicSharedMemorySize, SMEM_E1);
    cudaFuncSetAttribute(edge_hmma<256, 1>, cudaFuncAttributeMaxDynamicSharedMemorySize, SMEM_E2);

    int nsm = 148;
    cudaDeviceGetAttribute(&nsm, cudaDevAttrMultiProcessorCount, 0);

    cs_kernel<<<NG, HH>>>(charge, spin, emb_chg, emb_spin, W_cs, b_cs);
    node_kernel<<<nsm, 256, SMEM_NODE>>>(atomic_numbers, nde, nbatch, emb_atom,
                                         W_nd, b_nd, ln_g, ln_b, W_node, b_node);
    edge_hmma<192, 0><<<nsm, 512, SMEM_E1>>>(edist, edir, nullptr, W_edge, b_edge, nullptr);
    edge_hmma<256, 1><<<nsm, 512, SMEM_E2>>>(nullptr, nullptr, nsrc, W_ef, b_ef, out);
}

// round 9
// speedup vs baseline: 2.8072x; 1.0394x over previous
#include <cuda_runtime.h>
#include <cuda_bf16.h>
#include <cstdint>
#include <cstddef>

// ---------------- problem constants ----------------
#define NN     50000
#define NE     800000
#define NG     32
#define HH     128
#define NDD    16
#define EDD    128
#define DD2D   64

#define NT_E   (NE/256)     // 3125 edge tiles of 256
#define NT_N   (NN/16)      // 3125 node tiles of 16

// ---------------- scratch (device globals: no allocation allowed) ----------------
__device__ float g_cs[NG * HH];
// A operands pre-split into mma-fragment form:
//   frag[row*32 + ks*4 + q] = {hi(k,k+1), hi(k+8,k+9), lo(k,k+1), lo(k+8,k+9)}
//   where k = ks*16 + q*2
__device__ uint4 g_nfrag[(size_t)NN * 32];   //  25.6 MB (node features)
__device__ uint4 g_efrag[(size_t)NE * 32];   // 409.6 MB (edge attrs)

// ---------------- helpers ----------------
__device__ __forceinline__ float gelu_f(float x) {
    return 0.5f * x * (1.0f + erff(x * 0.70710678118654752440f));
}

// pack two f32 -> bf16x2 (lo half = a, hi half = b)
__device__ __forceinline__ uint32_t cvt2(float a, float b) {
    uint32_t r;
    asm("cvt.rn.bf16x2.f32 %0, %1, %2;" : "=r"(r) : "f"(b), "f"(a));
    return r;
}

// split a float2 pair into hi bf16x2 and lo bf16x2
__device__ __forceinline__ void split2(float2 v, uint32_t& hi, uint32_t& lo) {
    hi = cvt2(v.x, v.y);
    float fa = __uint_as_float(hi << 16);
    float fb = __uint_as_float(hi & 0xFFFF0000u);
    lo = cvt2(v.x - fa, v.y - fb);
}

__device__ __forceinline__ void mma_bf16(float c[4], const uint32_t a[4],
                                         uint32_t b0, uint32_t b1) {
    asm volatile("mma.sync.aligned.m16n8k16.row.col.f32.bf16.bf16.f32 "
                 "{%0,%1,%2,%3}, {%4,%5,%6,%7}, {%8,%9}, {%0,%1,%2,%3};"
                 : "+f"(c[0]), "+f"(c[1]), "+f"(c[2]), "+f"(c[3])
                 : "r"(a[0]), "r"(a[1]), "r"(a[2]), "r"(a[3]), "r"(b0), "r"(b1));
}

// build a W fragment table: sf[ks][nb][lane] = {bh0,bh1,bl0,bl1}
template<int KDIM>
__device__ __forceinline__ void build_wtable(uint4* sf, const float* __restrict__ W,
                                             int tid, int nthreads) {
    constexpr int NKS = KDIM / 16;
    for (int idx = tid; idx < NKS * 16 * 32; idx += nthreads) {
        int li = idx & 31, nb = (idx >> 5) & 15, ks = idx >> 9;
        int n  = nb * 8 + (li >> 2);
        int kg = ks * 16 + (li & 3) * 2;
        float2 w0 = make_float2(W[(size_t)kg * HH + n],       W[(size_t)(kg + 1) * HH + n]);
        float2 w1 = make_float2(W[(size_t)(kg + 8) * HH + n], W[(size_t)(kg + 9) * HH + n]);
        uint32_t h0, l0, h1, l1;
        split2(w0, h0, l0);
        split2(w1, h1, l1);
        sf[idx] = make_uint4(h0, h1, l0, l1);
    }
}

// ======================================================================
// Kernel 0: cs[g] = gelu(concat(emb_chg[charge], emb_spin[spin]) @ W_cs + b_cs)
// ======================================================================
__global__ void cs_kernel(const int* __restrict__ charge, const int* __restrict__ spin,
                          const float* __restrict__ emb_chg, const float* __restrict__ emb_spin,
                          const float* __restrict__ W_cs, const float* __restrict__ b_cs) {
    __shared__ float xv[2 * HH];
    int g = blockIdx.x, j = threadIdx.x;
    int c = charge[g], s = spin[g];
    xv[j]      = emb_chg[c * HH + j];
    xv[HH + j] = emb_spin[s * HH + j];
    __syncthreads();
    float acc = b_cs[j];
    #pragma unroll 8
    for (int k = 0; k < 2 * HH; k++) acc += xv[k] * W_cs[k * HH + j];
    g_cs[g * HH + j] = gelu_f(acc);
}

// ======================================================================
// Kernel 1: node features — embed/LN fp32, GEMM via HMMA hi/lo 3-pass.
// Output written directly in fragment form to g_nfrag.
// ======================================================================
#define SXS 264
#define SMEM_NODE (131072 + 16 * SXS * 4)

__global__ void __launch_bounds__(256, 1)
node_kernel(const int* __restrict__ an, const float* __restrict__ nde,
            const int* __restrict__ nbatch,
            const float* __restrict__ emb_atom, const float* __restrict__ W_nd,
            const float* __restrict__ b_nd, const float* __restrict__ ln_g,
            const float* __restrict__ ln_b, const float* __restrict__ W_node,
            const float* __restrict__ b_node) {
    extern __shared__ char dyn_smem[];
    uint4* sfW = (uint4*)dyn_smem;               // [16][16][32]
    float* sx  = (float*)(dyn_smem + 131072);    // [16][SXS]
    __shared__ float smu[16], srs[16];
    const int tid = threadIdx.x, lane = tid & 31, wid = tid >> 5;
    const int lr = lane >> 2, kc = (lane & 3) * 2;

    build_wtable<256>(sfW, W_node, tid, 256);
    __syncthreads();

    for (int t0 = blockIdx.x; t0 < NT_N; t0 += gridDim.x) {
        __syncthreads();   // sx reuse fence
        int n0 = t0 * 16;
        for (int idx = tid; idx < 16 * HH; idx += 256) {
            int n = idx >> 7, j = idx & 127;
            int node = n0 + n;
            float a = emb_atom[an[node] * HH + j];
            float accv = b_nd[j];
            const float* nrow = nde + node * NDD;
            #pragma unroll
            for (int k = 0; k < NDD; k++) accv += nrow[k] * W_nd[k * HH + j];
            sx[n * SXS + j]      = a;
            sx[n * SXS + HH + j] = gelu_f(accv);
        }
        __syncthreads();
        for (int n = wid; n < 16; n += 8) {
            float s1 = 0.f, s2 = 0.f;
            for (int k = lane; k < 256; k += 32) {
                float v = sx[n * SXS + k]; s1 += v; s2 += v * v;
            }
            #pragma unroll
            for (int o = 16; o > 0; o >>= 1) {
                s1 += __shfl_down_sync(0xffffffffu, s1, o);
                s2 += __shfl_down_sync(0xffffffffu, s2, o);
            }
            if (lane == 0) {
                float mu  = s1 * (1.f / 256.f);
                float var = s2 * (1.f / 256.f) - mu * mu;
                smu[n] = mu; srs[n] = rsqrtf(var + 1e-5f);
            }
        }
        __syncthreads();
        for (int idx = tid; idx < 16 * 256; idx += 256) {
            int n = idx >> 8, k = idx & 255;
            sx[n * SXS + k] =
                (sx[n * SXS + k] - smu[n]) * srs[n] * ln_g[k] + ln_b[k];
        }
        __syncthreads();
        // ---- GEMM [16,256]@[256,128] via HMMA; warp handles nb = 2*wid, 2*wid+1
        {
            float acc[2][4];
            #pragma unroll
            for (int i = 0; i < 2; i++) {
                float2 b = *(const float2*)(b_node + (wid * 2 + i) * 8 + kc);
                acc[i][0] = b.x; acc[i][1] = b.y; acc[i][2] = b.x; acc[i][3] = b.y;
            }
            #pragma unroll
            for (int ks = 0; ks < 16; ks++) {
                const float* x0 = sx + lr * SXS + ks * 16 + kc;
                const float* x1 = x0 + 8 * SXS;
                uint32_t ah[4], al[4];
                split2(*(const float2*)x0,       ah[0], al[0]);
                split2(*(const float2*)x1,       ah[1], al[1]);
                split2(*(const float2*)(x0 + 8), ah[2], al[2]);
                split2(*(const float2*)(x1 + 8), ah[3], al[3]);
                uint4 f0 = sfW[ks * 512 + (wid * 2 + 0) * 32 + lane];
                uint4 f1 = sfW[ks * 512 + (wid * 2 + 1) * 32 + lane];
                mma_bf16(acc[0], ah, f0.x, f0.y);
                mma_bf16(acc[1], ah, f1.x, f1.y);
                mma_bf16(acc[0], al, f0.x, f0.y);
                mma_bf16(acc[1], al, f1.x, f1.y);
                mma_bf16(acc[0], ah, f0.z, f0.w);
                mma_bf16(acc[1], ah, f1.z, f1.w);
            }
            // epilogue: gelu + cs add, then split to fragment form.
            // nb=2*wid covers k-part (cols wid*16+kc), nb=2*wid+1 covers k+8 part.
            const int node0 = n0 + lr, node1 = node0 + 8;
            const float* cs0 = g_cs + nbatch[node0] * HH;
            const float* cs1 = g_cs + nbatch[node1] * HH;
            const int col0 = wid * 16 + kc;
            const int col1 = col0 + 8;
            uint32_t h0, l0, h1, l1;
            float2 p, r;
            p.x = gelu_f(acc[0][0]) + cs0[col0]; p.y = gelu_f(acc[0][1]) + cs0[col0 + 1];
            r.x = gelu_f(acc[1][0]) + cs0[col1]; r.y = gelu_f(acc[1][1]) + cs0[col1 + 1];
            split2(p, h0, l0); split2(r, h1, l1);
            g_nfrag[(size_t)node0 * 32 + wid * 4 + (kc >> 1)] = make_uint4(h0, h1, l0, l1);
            p.x = gelu_f(acc[0][2]) + cs1[col0]; p.y = gelu_f(acc[0][3]) + cs1[col0 + 1];
            r.x = gelu_f(acc[1][2]) + cs1[col1]; r.y = gelu_f(acc[1][3]) + cs1[col1 + 1];
            split2(p, h0, l0); split2(r, h1, l1);
            g_nfrag[(size_t)node1 * 32 + wid * 4 + (kc >> 1)] = make_uint4(h0, h1, l0, l1);
        }
    }
}

// ======================================================================
// Edge kernel 1: eattr = gelu([edist|edir] @ W_edge + b_edge), K=192.
// 512 threads, 16 warps 8(m)x2(n), warp tile 32x64, tile = 256 edges.
// A split in-loop (raw fp32 inputs); OUTPUT stored in fragment form.
// ======================================================================
__global__ void __launch_bounds__(512, 1)
edge1_hmma(const float* __restrict__ P0, const float* __restrict__ P1,
           const float* __restrict__ W, const float* __restrict__ bias)
{
    constexpr int NKS = 12;
    extern __shared__ char dyn_smem[];
    uint4* sf = (uint4*)dyn_smem;          // [12][16][32]

    const int tid = threadIdx.x, lane = tid & 31, wid = tid >> 5;
    const int warp_m = wid & 7, warp_n = wid >> 3;
    const int lr = lane >> 2, kc = (lane & 3) * 2, q = lane & 3;

    build_wtable<192>(sf, W, tid, 512);
    __syncthreads();

    const uint4* wfl = sf + (size_t)warp_n * 8 * 32 + lane;

    for (int tile = blockIdx.x; tile < NT_E; tile += gridDim.x) {
        const int e0 = tile * 256;
        const int mb0 = e0 + warp_m * 32 + lr;   // rows: mb0 + r*8, r=0..3
        const float* pA = P0 + (size_t)mb0 * EDD + kc;
        const float* pB = P1 + (size_t)mb0 * DD2D + kc;

        float acc[2][8][4];
        #pragma unroll
        for (int i = 0; i < 8; i++) {
            float2 b = *(const float2*)(bias + (warp_n * 8 + i) * 8 + kc);
            #pragma unroll
            for (int mf = 0; mf < 2; mf++) {
                acc[mf][i][0] = b.x; acc[mf][i][1] = b.y;
                acc[mf][i][2] = b.x; acc[mf][i][3] = b.y;
            }
        }

        float2 v[4][2];
        #define LOADA(KG)                                                          \
        {                                                                          \
            _Pragma("unroll")                                                      \
            for (int r = 0; r < 4; r++) {                                          \
                const float* qq = ((KG) < 128) ? pA + r * 8 * EDD + (KG)           \
                                               : pB + r * 8 * DD2D + ((KG) - 128); \
                v[r][0] = *(const float2*)qq;                                      \
                v[r][1] = *(const float2*)(qq + 8);                                \
            }                                                                      \
        }

        LOADA(0);

        #pragma unroll
        for (int ks = 0; ks < NKS; ks++) {
            uint32_t ah0[4], al0[4], ah1[4], al1[4];
            split2(v[0][0], ah0[0], al0[0]);
            split2(v[1][0], ah0[1], al0[1]);
            split2(v[0][1], ah0[2], al0[2]);
            split2(v[1][1], ah0[3], al0[3]);
            split2(v[2][0], ah1[0], al1[0]);
            split2(v[3][0], ah1[1], al1[1]);
            split2(v[2][1], ah1[2], al1[2]);
            split2(v[3][1], ah1[3], al1[3]);
            if (ks + 1 < NKS) LOADA((ks + 1) * 16);

            const uint4* wk = wfl + ks * 512;
            #pragma unroll
            for (int h = 0; h < 4; h++) {
                uint4 f0 = wk[(h * 2 + 0) * 32];
                uint4 f1 = wk[(h * 2 + 1) * 32];
                mma_bf16(acc[0][h * 2 + 0], ah0, f0.x, f0.y);
                mma_bf16(acc[0][h * 2 + 1], ah0, f1.x, f1.y);
                mma_bf16(acc[1][h * 2 + 0], ah1, f0.x, f0.y);
                mma_bf16(acc[1][h * 2 + 1], ah1, f1.x, f1.y);
                mma_bf16(acc[0][h * 2 + 0], al0, f0.x, f0.y);
                mma_bf16(acc[0][h * 2 + 1], al0, f1.x, f1.y);
                mma_bf16(acc[1][h * 2 + 0], al1, f0.x, f0.y);
                mma_bf16(acc[1][h * 2 + 1], al1, f1.x, f1.y);
                mma_bf16(acc[0][h * 2 + 0], ah0, f0.z, f0.w);
                mma_bf16(acc[0][h * 2 + 1], ah0, f1.z, f1.w);
                mma_bf16(acc[1][h * 2 + 0], ah1, f0.z, f0.w);
                mma_bf16(acc[1][h * 2 + 1], ah1, f1.z, f1.w);
            }
        }
        #undef LOADA

        // ---- epilogue: gelu + split to fragment form.
        // nb = warp_n*8 + i; pair (i=2j, i=2j+1) -> ksIdx = warp_n*4 + j.
        #pragma unroll
        for (int mf = 0; mf < 2; mf++) {
            const size_t ra = (size_t)(mb0 + mf * 16);
            #pragma unroll
            for (int j = 0; j < 4; j++) {
                const int i0 = 2 * j, i1 = 2 * j + 1;
                const int ksIdx = warp_n * 4 + j;
                uint32_t h0, l0, h1, l1;
                float2 a, b;
                a.x = gelu_f(acc[mf][i0][0]); a.y = gelu_f(acc[mf][i0][1]);
                b.x = gelu_f(acc[mf][i1][0]); b.y = gelu_f(acc[mf][i1][1]);
                split2(a, h0, l0); split2(b, h1, l1);
                g_efrag[ra * 32 + ksIdx * 4 + q] = make_uint4(h0, h1, l0, l1);
                a.x = gelu_f(acc[mf][i0][2]); a.y = gelu_f(acc[mf][i0][3]);
                b.x = gelu_f(acc[mf][i1][2]); b.y = gelu_f(acc[mf][i1][3]);
                split2(a, h0, l0); split2(b, h1, l1);
                g_efrag[(ra + 8) * 32 + ksIdx * 4 + q] = make_uint4(h0, h1, l0, l1);
            }
        }
    }
}

// ======================================================================
// Edge kernel 2: out = gelu([node[src]|eattr] @ W_ef + b_ef), K=256.
// A comes PRE-SPLIT in fragment form (g_nfrag for ks<8, g_efrag for ks>=8):
// per k-step only 4x LDG.128 + 8x LDS.128 + 48 HMMA — no split, no ALU chains.
// ======================================================================
__global__ void __launch_bounds__(512, 1)
edge2_hmma(const int* __restrict__ srcIdx, const float* __restrict__ W,
           const float* __restrict__ bias, float* __restrict__ outp)
{
    extern __shared__ char dyn_smem[];
    uint4* sf = (uint4*)dyn_smem;          // [16][16][32]

    const int tid = threadIdx.x, lane = tid & 31, wid = tid >> 5;
    const int warp_m = wid & 7, warp_n = wid >> 3;
    const int lr = lane >> 2, kc = (lane & 3) * 2, q = lane & 3;

    build_wtable<256>(sf, W, tid, 512);
    __syncthreads();

    const uint4* wfl = sf + (size_t)warp_n * 8 * 32 + lane;

    for (int tile = blockIdx.x; tile < NT_E; tile += gridDim.x) {
        const int e0 = tile * 256;
        const int mb0 = e0 + warp_m * 32 + lr;   // rows: mb0 + r*8, r=0..3

        uint32_t offN[4];
        #pragma unroll
        for (int r = 0; r < 4; r++)
            offN[r] = (uint32_t)srcIdx[mb0 + r * 8] * 32;
        const uint4* nbase = g_nfrag + q;
        const uint4* ebase = g_efrag + (size_t)mb0 * 32 + q;

        float acc[2][8][4];
        #pragma unroll
        for (int i = 0; i < 8; i++) {
            float2 b = *(const float2*)(bias + (warp_n * 8 + i) * 8 + kc);
            #pragma unroll
            for (int mf = 0; mf < 2; mf++) {
                acc[mf][i][0] = b.x; acc[mf][i][1] = b.y;
                acc[mf][i][2] = b.x; acc[mf][i][3] = b.y;
            }
        }

        uint4 va[4], vb[4];
        #define LOADA(KS, BUF)                                                   \
        {                                                                        \
            if ((KS) < 8) {                                                      \
                _Pragma("unroll")                                                \
                for (int r = 0; r < 4; r++) BUF[r] = nbase[offN[r] + (KS) * 4];  \
            } else {                                                             \
                _Pragma("unroll")                                                \
                for (int r = 0; r < 4; r++) BUF[r] = ebase[r * 256 + ((KS) - 8) * 4]; \
            }                                                                    \
        }

        LOADA(0, va);

        #pragma unroll
        for (int ks = 0; ks < 16; ks++) {
            uint4* cur = (ks & 1) ? vb : va;
            uint4* nxt = (ks & 1) ? va : vb;
            if (ks + 1 < 16) LOADA(ks + 1, nxt);

            // a-operands by register selection — zero instructions
            uint32_t ah0[4] = {cur[0].x, cur[1].x, cur[0].y, cur[1].y};
            uint32_t al0[4] = {cur[0].z, cur[1].z, cur[0].w, cur[1].w};
            uint32_t ah1[4] = {cur[2].x, cur[3].x, cur[2].y, cur[3].y};
            uint32_t al1[4] = {cur[2].z, cur[3].z, cur[2].w, cur[3].w};

            const uint4* wk = wfl + ks * 512;
            #pragma unroll
            for (int h = 0; h < 4; h++) {
                uint4 f0 = wk[(h * 2 + 0) * 32];
                uint4 f1 = wk[(h * 2 + 1) * 32];
                mma_bf16(acc[0][h * 2 + 0], ah0, f0.x, f0.y);
                mma_bf16(acc[0][h * 2 + 1], ah0, f1.x, f1.y);
                mma_bf16(acc[1][h * 2 + 0], ah1, f0.x, f0.y);
                mma_bf16(acc[1][h * 2 + 1], ah1, f1.x, f1.y);
                mma_bf16(acc[0][h * 2 + 0], al0, f0.x, f0.y);
                mma_bf16(acc[0][h * 2 + 1], al0, f1.x, f1.y);
                mma_bf16(acc[1][h * 2 + 0], al1, f0.x, f0.y);
                mma_bf16(acc[1][h * 2 + 1], al1, f1.x, f1.y);
                mma_bf16(acc[0][h * 2 + 0], ah0, f0.z, f0.w);
                mma_bf16(acc[0][h * 2 + 1], ah0, f1.z, f1.w);
                mma_bf16(acc[1][h * 2 + 0], ah1, f0.z, f0.w);
                mma_bf16(acc[1][h * 2 + 1], ah1, f1.z, f1.w);
            }
        }
        #undef LOADA

        // ---- epilogue: gelu + fp32 store to output ----
        #pragma unroll
        for (int mf = 0; mf < 2; mf++) {
            const int ra = mb0 + mf * 16;
            #pragma unroll
            for (int i = 0; i < 8; i++) {
                const int col = (warp_n * 8 + i) * 8 + kc;
                float2 o0, o1;
                o0.x = gelu_f(acc[mf][i][0]); o0.y = gelu_f(acc[mf][i][1]);
                o1.x = gelu_f(acc[mf][i][2]); o1.y = gelu_f(acc[mf][i][3]);
                *(float2*)(outp + (size_t)ra * HH + col)       = o0;
                *(float2*)(outp + (size_t)(ra + 8) * HH + col) = o1;
            }
        }
    }
}

#define SMEM_E1 (12 * 16 * 32 * 16)   //  98,304 B
#define SMEM_E2 (16 * 16 * 32 * 16)   // 131,072 B

// ======================================================================
// launch
// ======================================================================
extern "C" void kernel_launch(void* const* d_in, const int* in_sizes, int n_in,
                              void* d_out, int out_size) {
    const int*   atomic_numbers = (const int*)  d_in[0];
    const float* nde            = (const float*)d_in[1];
    const float* edist          = (const float*)d_in[2];
    const float* edir           = (const float*)d_in[3];
    const int*   charge         = (const int*)  d_in[4];
    const int*   spin           = (const int*)  d_in[5];
    const int*   nbatch         = (const int*)  d_in[6];
    const int*   nsrc           = (const int*)  d_in[7];
    const float* emb_atom       = (const float*)d_in[8];
    const float* W_nd           = (const float*)d_in[9];
    const float* b_nd           = (const float*)d_in[10];
    const float* ln_g           = (const float*)d_in[11];
    const float* ln_b           = (const float*)d_in[12];
    const float* W_node         = (const float*)d_in[13];
    const float* b_node         = (const float*)d_in[14];
    const float* emb_chg        = (const float*)d_in[15];
    const float* emb_spin       = (const float*)d_in[16];
    const float* W_cs           = (const float*)d_in[17];
    const float* b_cs           = (const float*)d_in[18];
    const float* W_edge         = (const float*)d_in[19];
    const float* b_edge         = (const float*)d_in[20];
    const float* W_ef           = (const float*)d_in[21];
    const float* b_ef           = (const float*)d_in[22];
    float* out = (float*)d_out;

    cudaFuncSetAttribute(node_kernel, cudaFuncAttributeMaxDynamicSharedMemorySize, SMEM_NODE);
    cudaFuncSetAttribute(edge1_hmma,  cudaFuncAttributeMaxDynamicSharedMemorySize, SMEM_E1);
    cudaFuncSetAttribute(edge2_hmma,  cudaFuncAttributeMaxDynamicSharedMemorySize, SMEM_E2);

    int nsm = 148;
    cudaDeviceGetAttribute(&nsm, cudaDevAttrMultiProcessorCount, 0);

    cs_kernel<<<NG, HH>>>(charge, spin, emb_chg, emb_spin, W_cs, b_cs);
    node_kernel<<<nsm, 256, SMEM_NODE>>>(atomic_numbers, nde, nbatch, emb_atom,
                                         W_nd, b_nd, ln_g, ln_b, W_node, b_node);
    edge1_hmma<<<nsm, 512, SMEM_E1>>>(edist, edir, W_edge, b_edge);
    edge2_hmma<<<nsm, 512, SMEM_E2>>>(nsrc, W_ef, b_ef, out);
}

// round 10
// speedup vs baseline: 3.4170x; 1.2172x over previous
#include <cuda_runtime.h>
#include <cuda_fp16.h>
#include <cstdint>
#include <cstddef>

// ---------------- problem constants ----------------
#define NN     50000
#define NE     800000
#define NG     32
#define HH     128
#define NDD    16
#define EDD    128
#define DD2D   64

#define NT_E   (NE/256)     // 3125 edge tiles of 256
#define NT_N   (NN/16)      // 3125 node tiles of 16

// ---------------- scratch (device globals: no allocation allowed) ----------------
__device__ float g_cs[NG * HH];
// A operands pre-converted to fp16 mma-fragment form (single-rounded):
//   frag[row*32 + ks*4 + q] = {f16x2(k,k+1), f16x2(k+8,k+9)}, k = ks*16 + q*2
__device__ uint2 g_nfrag[(size_t)NN * 32];   //  12.8 MB (node features)
__device__ uint2 g_efrag[(size_t)NE * 32];   // 204.8 MB (edge attrs)

// ---------------- helpers ----------------
__device__ __forceinline__ float gelu_f(float x) {
    return 0.5f * x * (1.0f + erff(x * 0.70710678118654752440f));
}

// pack two f32 -> f16x2 (lo half = a, hi half = b)
__device__ __forceinline__ uint32_t cvt2h(float a, float b) {
    uint32_t r;
    asm("cvt.rn.f16x2.f32 %0, %1, %2;" : "=r"(r) : "f"(b), "f"(a));
    return r;
}

// split a float2 pair into hi f16x2 and lo (residual) f16x2
__device__ __forceinline__ void split2h(float2 v, uint32_t& hi, uint32_t& lo) {
    hi = cvt2h(v.x, v.y);
    __half2 h = *reinterpret_cast<__half2*>(&hi);
    float2 f = __half22float2(h);          // f.x = lo half (=v.x rounded)
    lo = cvt2h(v.x - f.x, v.y - f.y);
}

__device__ __forceinline__ void mma_f16(float c[4], const uint32_t a[4],
                                        uint32_t b0, uint32_t b1) {
    asm volatile("mma.sync.aligned.m16n8k16.row.col.f32.f16.f16.f32 "
                 "{%0,%1,%2,%3}, {%4,%5,%6,%7}, {%8,%9}, {%0,%1,%2,%3};"
                 : "+f"(c[0]), "+f"(c[1]), "+f"(c[2]), "+f"(c[3])
                 : "r"(a[0]), "r"(a[1]), "r"(a[2]), "r"(a[3]), "r"(b0), "r"(b1));
}

// build a W fragment table (fp16 hi/lo): sf[ks][nb][lane] = {bh0,bh1,bl0,bl1}
template<int KDIM>
__device__ __forceinline__ void build_wtable(uint4* sf, const float* __restrict__ W,
                                             int tid, int nthreads) {
    constexpr int NKS = KDIM / 16;
    for (int idx = tid; idx < NKS * 16 * 32; idx += nthreads) {
        int li = idx & 31, nb = (idx >> 5) & 15, ks = idx >> 9;
        int n  = nb * 8 + (li >> 2);
        int kg = ks * 16 + (li & 3) * 2;
        float2 w0 = make_float2(W[(size_t)kg * HH + n],       W[(size_t)(kg + 1) * HH + n]);
        float2 w1 = make_float2(W[(size_t)(kg + 8) * HH + n], W[(size_t)(kg + 9) * HH + n]);
        uint32_t h0, l0, h1, l1;
        split2h(w0, h0, l0);
        split2h(w1, h1, l1);
        sf[idx] = make_uint4(h0, h1, l0, l1);
    }
}

// ======================================================================
// Kernel 0: cs[g] = gelu(concat(emb_chg[charge], emb_spin[spin]) @ W_cs + b_cs)
// ======================================================================
__global__ void cs_kernel(const int* __restrict__ charge, const int* __restrict__ spin,
                          const float* __restrict__ emb_chg, const float* __restrict__ emb_spin,
                          const float* __restrict__ W_cs, const float* __restrict__ b_cs) {
    __shared__ float xv[2 * HH];
    int g = blockIdx.x, j = threadIdx.x;
    int c = charge[g], s = spin[g];
    xv[j]      = emb_chg[c * HH + j];
    xv[HH + j] = emb_spin[s * HH + j];
    __syncthreads();
    float acc = b_cs[j];
    #pragma unroll 8
    for (int k = 0; k < 2 * HH; k++) acc += xv[k] * W_cs[k * HH + j];
    g_cs[g * HH + j] = gelu_f(acc);
}

// ======================================================================
// Kernel 1: node features — embed/LN fp32, GEMM via fp16 HMMA 2-pass
// (A single-rounded fp16, W hi+lo). Output -> g_nfrag (fp16 fragments).
// ======================================================================
#define SXS 264
#define SMEM_NODE (131072 + 16 * SXS * 4)

__global__ void __launch_bounds__(256, 1)
node_kernel(const int* __restrict__ an, const float* __restrict__ nde,
            const int* __restrict__ nbatch,
            const float* __restrict__ emb_atom, const float* __restrict__ W_nd,
            const float* __restrict__ b_nd, const float* __restrict__ ln_g,
            const float* __restrict__ ln_b, const float* __restrict__ W_node,
            const float* __restrict__ b_node) {
    extern __shared__ char dyn_smem[];
    uint4* sfW = (uint4*)dyn_smem;               // [16][16][32]
    float* sx  = (float*)(dyn_smem + 131072);    // [16][SXS]
    __shared__ float smu[16], srs[16];
    const int tid = threadIdx.x, lane = tid & 31, wid = tid >> 5;
    const int lr = lane >> 2, kc = (lane & 3) * 2;

    build_wtable<256>(sfW, W_node, tid, 256);
    __syncthreads();

    for (int t0 = blockIdx.x; t0 < NT_N; t0 += gridDim.x) {
        __syncthreads();   // sx reuse fence
        int n0 = t0 * 16;
        for (int idx = tid; idx < 16 * HH; idx += 256) {
            int n = idx >> 7, j = idx & 127;
            int node = n0 + n;
            float a = emb_atom[an[node] * HH + j];
            float accv = b_nd[j];
            const float* nrow = nde + node * NDD;
            #pragma unroll
            for (int k = 0; k < NDD; k++) accv += nrow[k] * W_nd[k * HH + j];
            sx[n * SXS + j]      = a;
            sx[n * SXS + HH + j] = gelu_f(accv);
        }
        __syncthreads();
        for (int n = wid; n < 16; n += 8) {
            float s1 = 0.f, s2 = 0.f;
            for (int k = lane; k < 256; k += 32) {
                float v = sx[n * SXS + k]; s1 += v; s2 += v * v;
            }
            #pragma unroll
            for (int o = 16; o > 0; o >>= 1) {
                s1 += __shfl_down_sync(0xffffffffu, s1, o);
                s2 += __shfl_down_sync(0xffffffffu, s2, o);
            }
            if (lane == 0) {
                float mu  = s1 * (1.f / 256.f);
                float var = s2 * (1.f / 256.f) - mu * mu;
                smu[n] = mu; srs[n] = rsqrtf(var + 1e-5f);
            }
        }
        __syncthreads();
        for (int idx = tid; idx < 16 * 256; idx += 256) {
            int n = idx >> 8, k = idx & 255;
            sx[n * SXS + k] =
                (sx[n * SXS + k] - smu[n]) * srs[n] * ln_g[k] + ln_b[k];
        }
        __syncthreads();
        // ---- GEMM [16,256]@[256,128]; warp handles nb = 2*wid, 2*wid+1
        {
            float acc[2][4];
            #pragma unroll
            for (int i = 0; i < 2; i++) {
                float2 b = *(const float2*)(b_node + (wid * 2 + i) * 8 + kc);
                acc[i][0] = b.x; acc[i][1] = b.y; acc[i][2] = b.x; acc[i][3] = b.y;
            }
            #pragma unroll
            for (int ks = 0; ks < 16; ks++) {
                const float* x0 = sx + lr * SXS + ks * 16 + kc;
                const float* x1 = x0 + 8 * SXS;
                uint32_t ah[4];
                ah[0] = cvt2h(x0[0], x0[1]);
                ah[1] = cvt2h(x1[0], x1[1]);
                ah[2] = cvt2h(x0[8], x0[9]);
                ah[3] = cvt2h(x1[8], x1[9]);
                uint4 f0 = sfW[ks * 512 + (wid * 2 + 0) * 32 + lane];
                uint4 f1 = sfW[ks * 512 + (wid * 2 + 1) * 32 + lane];
                mma_f16(acc[0], ah, f0.x, f0.y);
                mma_f16(acc[1], ah, f1.x, f1.y);
                mma_f16(acc[0], ah, f0.z, f0.w);
                mma_f16(acc[1], ah, f1.z, f1.w);
            }
            // epilogue: gelu + cs add, convert to fp16 fragment form.
            const int node0 = n0 + lr, node1 = node0 + 8;
            const float* cs0 = g_cs + nbatch[node0] * HH;
            const float* cs1 = g_cs + nbatch[node1] * HH;
            const int col0 = wid * 16 + kc;
            const int col1 = col0 + 8;
            uint32_t h0, h1;
            h0 = cvt2h(gelu_f(acc[0][0]) + cs0[col0], gelu_f(acc[0][1]) + cs0[col0 + 1]);
            h1 = cvt2h(gelu_f(acc[1][0]) + cs0[col1], gelu_f(acc[1][1]) + cs0[col1 + 1]);
            g_nfrag[(size_t)node0 * 32 + wid * 4 + (kc >> 1)] = make_uint2(h0, h1);
            h0 = cvt2h(gelu_f(acc[0][2]) + cs1[col0], gelu_f(acc[0][3]) + cs1[col0 + 1]);
            h1 = cvt2h(gelu_f(acc[1][2]) + cs1[col1], gelu_f(acc[1][3]) + cs1[col1 + 1]);
            g_nfrag[(size_t)node1 * 32 + wid * 4 + (kc >> 1)] = make_uint2(h0, h1);
        }
    }
}

// ======================================================================
// Edge kernel 1: eattr = gelu([edist|edir] @ W_edge + b_edge), K=192.
// 512 threads, 16 warps 8(m)x2(n), warp tile 32x64, tile = 256 edges.
// A converted in-loop to single fp16 (no residual); W hi+lo, 2 passes.
// Output stored in fp16 fragment form.
// ======================================================================
__global__ void __launch_bounds__(512, 1)
edge1_hmma(const float* __restrict__ P0, const float* __restrict__ P1,
           const float* __restrict__ W, const float* __restrict__ bias)
{
    constexpr int NKS = 12;
    extern __shared__ char dyn_smem[];
    uint4* sf = (uint4*)dyn_smem;          // [12][16][32]

    const int tid = threadIdx.x, lane = tid & 31, wid = tid >> 5;
    const int warp_m = wid & 7, warp_n = wid >> 3;
    const int lr = lane >> 2, kc = (lane & 3) * 2, q = lane & 3;

    build_wtable<192>(sf, W, tid, 512);
    __syncthreads();

    const uint4* wfl = sf + (size_t)warp_n * 8 * 32 + lane;

    for (int tile = blockIdx.x; tile < NT_E; tile += gridDim.x) {
        const int e0 = tile * 256;
        const int mb0 = e0 + warp_m * 32 + lr;   // rows: mb0 + r*8, r=0..3
        const float* pA = P0 + (size_t)mb0 * EDD + kc;
        const float* pB = P1 + (size_t)mb0 * DD2D + kc;

        float acc[2][8][4];
        #pragma unroll
        for (int i = 0; i < 8; i++) {
            float2 b = *(const float2*)(bias + (warp_n * 8 + i) * 8 + kc);
            #pragma unroll
            for (int mf = 0; mf < 2; mf++) {
                acc[mf][i][0] = b.x; acc[mf][i][1] = b.y;
                acc[mf][i][2] = b.x; acc[mf][i][3] = b.y;
            }
        }

        float2 v[4][2];
        #define LOADA(KG)                                                          \
        {                                                                          \
            _Pragma("unroll")                                                      \
            for (int r = 0; r < 4; r++) {                                          \
                const float* qq = ((KG) < 128) ? pA + r * 8 * EDD + (KG)           \
                                               : pB + r * 8 * DD2D + ((KG) - 128); \
                v[r][0] = *(const float2*)qq;                                      \
                v[r][1] = *(const float2*)(qq + 8);                                \
            }                                                                      \
        }

        LOADA(0);

        #pragma unroll
        for (int ks = 0; ks < NKS; ks++) {
            uint32_t ah0[4], ah1[4];
            ah0[0] = cvt2h(v[0][0].x, v[0][0].y);
            ah0[1] = cvt2h(v[1][0].x, v[1][0].y);
            ah0[2] = cvt2h(v[0][1].x, v[0][1].y);
            ah0[3] = cvt2h(v[1][1].x, v[1][1].y);
            ah1[0] = cvt2h(v[2][0].x, v[2][0].y);
            ah1[1] = cvt2h(v[3][0].x, v[3][0].y);
            ah1[2] = cvt2h(v[2][1].x, v[2][1].y);
            ah1[3] = cvt2h(v[3][1].x, v[3][1].y);
            if (ks + 1 < NKS) LOADA((ks + 1) * 16);

            const uint4* wk = wfl + ks * 512;
            #pragma unroll
            for (int h = 0; h < 4; h++) {
                uint4 f0 = wk[(h * 2 + 0) * 32];
                uint4 f1 = wk[(h * 2 + 1) * 32];
                mma_f16(acc[0][h * 2 + 0], ah0, f0.x, f0.y);
                mma_f16(acc[0][h * 2 + 1], ah0, f1.x, f1.y);
                mma_f16(acc[1][h * 2 + 0], ah1, f0.x, f0.y);
                mma_f16(acc[1][h * 2 + 1], ah1, f1.x, f1.y);
                mma_f16(acc[0][h * 2 + 0], ah0, f0.z, f0.w);
                mma_f16(acc[0][h * 2 + 1], ah0, f1.z, f1.w);
                mma_f16(acc[1][h * 2 + 0], ah1, f0.z, f0.w);
                mma_f16(acc[1][h * 2 + 1], ah1, f1.z, f1.w);
            }
        }
        #undef LOADA

        // ---- epilogue: gelu, convert to fp16 fragments.
        // nb pair (i0=2j, i1=2j+1) -> ksIdx = warp_n*4 + j.
        #pragma unroll
        for (int mf = 0; mf < 2; mf++) {
            const size_t ra = (size_t)(mb0 + mf * 16);
            #pragma unroll
            for (int j = 0; j < 4; j++) {
                const int i0 = 2 * j, i1 = 2 * j + 1;
                const int ksIdx = warp_n * 4 + j;
                uint32_t h0, h1;
                h0 = cvt2h(gelu_f(acc[mf][i0][0]), gelu_f(acc[mf][i0][1]));
                h1 = cvt2h(gelu_f(acc[mf][i1][0]), gelu_f(acc[mf][i1][1]));
                g_efrag[ra * 32 + ksIdx * 4 + q] = make_uint2(h0, h1);
                h0 = cvt2h(gelu_f(acc[mf][i0][2]), gelu_f(acc[mf][i0][3]));
                h1 = cvt2h(gelu_f(acc[mf][i1][2]), gelu_f(acc[mf][i1][3]));
                g_efrag[(ra + 8) * 32 + ksIdx * 4 + q] = make_uint2(h0, h1);
            }
        }
    }
}

// ======================================================================
// Edge kernel 2: out = gelu([node[src]|eattr] @ W_ef + b_ef), K=256.
// A comes PRE-CONVERTED fp16 fragments (g_nfrag ks<8, g_efrag ks>=8):
// per k-step 4x LDG.64 + 8x LDS.128 + 32 HMMA, W hi+lo 2-pass.
// ======================================================================
__global__ void __launch_bounds__(512, 1)
edge2_hmma(const int* __restrict__ srcIdx, const float* __restrict__ W,
           const float* __restrict__ bias, float* __restrict__ outp)
{
    extern __shared__ char dyn_smem[];
    uint4* sf = (uint4*)dyn_smem;          // [16][16][32]

    const int tid = threadIdx.x, lane = tid & 31, wid = tid >> 5;
    const int warp_m = wid & 7, warp_n = wid >> 3;
    const int lr = lane >> 2, kc = (lane & 3) * 2, q = lane & 3;

    build_wtable<256>(sf, W, tid, 512);
    __syncthreads();

    const uint4* wfl = sf + (size_t)warp_n * 8 * 32 + lane;

    for (int tile = blockIdx.x; tile < NT_E; tile += gridDim.x) {
        const int e0 = tile * 256;
        const int mb0 = e0 + warp_m * 32 + lr;   // rows: mb0 + r*8, r=0..3

        uint32_t offN[4];
        #pragma unroll
        for (int r = 0; r < 4; r++)
            offN[r] = (uint32_t)srcIdx[mb0 + r * 8] * 32;
        const uint2* nbase = g_nfrag + q;
        const uint2* ebase = g_efrag + (size_t)mb0 * 32 + q;

        float acc[2][8][4];
        #pragma unroll
        for (int i = 0; i < 8; i++) {
            float2 b = *(const float2*)(bias + (warp_n * 8 + i) * 8 + kc);
            #pragma unroll
            for (int mf = 0; mf < 2; mf++) {
                acc[mf][i][0] = b.x; acc[mf][i][1] = b.y;
                acc[mf][i][2] = b.x; acc[mf][i][3] = b.y;
            }
        }

        uint2 va[4], vb[4];
        #define LOADA(KS, BUF)                                                        \
        {                                                                             \
            if ((KS) < 8) {                                                           \
                _Pragma("unroll")                                                     \
                for (int r = 0; r < 4; r++) BUF[r] = nbase[offN[r] + (KS) * 4];       \
            } else {                                                                  \
                _Pragma("unroll")                                                     \
                for (int r = 0; r < 4; r++) BUF[r] = ebase[r * 256 + ((KS) - 8) * 4]; \
            }                                                                         \
        }

        LOADA(0, va);

        #pragma unroll
        for (int ks = 0; ks < 16; ks++) {
            uint2* cur = (ks & 1) ? vb : va;
            uint2* nxt = (ks & 1) ? va : vb;
            if (ks + 1 < 16) LOADA(ks + 1, nxt);

            // a-operands by register selection — zero instructions
            uint32_t ah0[4] = {cur[0].x, cur[1].x, cur[0].y, cur[1].y};
            uint32_t ah1[4] = {cur[2].x, cur[3].x, cur[2].y, cur[3].y};

            const uint4* wk = wfl + ks * 512;
            #pragma unroll
            for (int h = 0; h < 4; h++) {
                uint4 f0 = wk[(h * 2 + 0) * 32];
                uint4 f1 = wk[(h * 2 + 1) * 32];
                mma_f16(acc[0][h * 2 + 0], ah0, f0.x, f0.y);
                mma_f16(acc[0][h * 2 + 1], ah0, f1.x, f1.y);
                mma_f16(acc[1][h * 2 + 0], ah1, f0.x, f0.y);
                mma_f16(acc[1][h * 2 + 1], ah1, f1.x, f1.y);
                mma_f16(acc[0][h * 2 + 0], ah0, f0.z, f0.w);
                mma_f16(acc[0][h * 2 + 1], ah0, f1.z, f1.w);
                mma_f16(acc[1][h * 2 + 0], ah1, f0.z, f0.w);
                mma_f16(acc[1][h * 2 + 1], ah1, f1.z, f1.w);
            }
        }
        #undef LOADA

        // ---- epilogue: gelu + fp32 store to output ----
        #pragma unroll
        for (int mf = 0; mf < 2; mf++) {
            const int ra = mb0 + mf * 16;
            #pragma unroll
            for (int i = 0; i < 8; i++) {
                const int col = (warp_n * 8 + i) * 8 + kc;
                float2 o0, o1;
                o0.x = gelu_f(acc[mf][i][0]); o0.y = gelu_f(acc[mf][i][1]);
                o1.x = gelu_f(acc[mf][i][2]); o1.y = gelu_f(acc[mf][i][3]);
                *(float2*)(outp + (size_t)ra * HH + col)       = o0;
                *(float2*)(outp + (size_t)(ra + 8) * HH + col) = o1;
            }
        }
    }
}

#define SMEM_E1 (12 * 16 * 32 * 16)   //  98,304 B
#define SMEM_E2 (16 * 16 * 32 * 16)   // 131,072 B

// ======================================================================
// launch
// ======================================================================
extern "C" void kernel_launch(void* const* d_in, const int* in_sizes, int n_in,
                              void* d_out, int out_size) {
    const int*   atomic_numbers = (const int*)  d_in[0];
    const float* nde            = (const float*)d_in[1];
    const float* edist          = (const float*)d_in[2];
    const float* edir           = (const float*)d_in[3];
    const int*   charge         = (const int*)  d_in[4];
    const int*   spin           = (const int*)  d_in[5];
    const int*   nbatch         = (const int*)  d_in[6];
    const int*   nsrc           = (const int*)  d_in[7];
    const float* emb_atom       = (const float*)d_in[8];
    const float* W_nd           = (const float*)d_in[9];
    const float* b_nd           = (const float*)d_in[10];
    const float* ln_g           = (const float*)d_in[11];
    const float* ln_b           = (const float*)d_in[12];
    const float* W_node         = (const float*)d_in[13];
    const float* b_node         = (const float*)d_in[14];
    const float* emb_chg        = (const float*)d_in[15];
    const float* emb_spin       = (const float*)d_in[16];
    const float* W_cs           = (const float*)d_in[17];
    const float* b_cs           = (const float*)d_in[18];
    const float* W_edge         = (const float*)d_in[19];
    const float* b_edge         = (const float*)d_in[20];
    const float* W_ef           = (const float*)d_in[21];
    const float* b_ef           = (const float*)d_in[22];
    float* out = (float*)d_out;

    cudaFuncSetAttribute(node_kernel, cudaFuncAttributeMaxDynamicSharedMemorySize, SMEM_NODE);
    cudaFuncSetAttribute(edge1_hmma,  cudaFuncAttributeMaxDynamicSharedMemorySize, SMEM_E1);
    cudaFuncSetAttribute(edge2_hmma,  cudaFuncAttributeMaxDynamicSharedMemorySize, SMEM_E2);

    int nsm = 148;
    cudaDeviceGetAttribute(&nsm, cudaDevAttrMultiProcessorCount, 0);

    cs_kernel<<<NG, HH>>>(charge, spin, emb_chg, emb_spin, W_cs, b_cs);
    node_kernel<<<nsm, 256, SMEM_NODE>>>(atomic_numbers, nde, nbatch, emb_atom,
                                         W_nd, b_nd, ln_g, ln_b, W_node, b_node);
    edge1_hmma<<<nsm, 512, SMEM_E1>>>(edist, edir, W_edge, b_edge);
    edge2_hmma<<<nsm, 512, SMEM_E2>>>(nsrc, W_ef, b_ef, out);
}

// round 11
// speedup vs baseline: 4.0675x; 1.1904x over previous
#include <cuda_runtime.h>
#include <cuda_fp16.h>
#include <cstdint>
#include <cstddef>

// ---------------- problem constants ----------------
#define NN     50000
#define NE     800000
#define NG     32
#define HH     128
#define NDD    16
#define EDD    128
#define DD2D   64

#define NT_E   (NE/256)     // 3125 edge tiles of 256
#define NT_N   (NN/16)      // 3125 node tiles of 16

// ---------------- scratch (device globals: no allocation allowed) ----------------
__device__ float g_cs[NG * HH];
// A operands pre-converted to fp16 mma-fragment form (single-rounded):
//   frag[row*32 + ks*4 + q] = {f16x2(k,k+1), f16x2(k+8,k+9)}, k = ks*16 + q*2
__device__ uint2 g_nfrag[(size_t)NN * 32];   //  12.8 MB (node features)
__device__ uint2 g_efrag[(size_t)NE * 32];   // 204.8 MB (edge attrs)

// ---------------- helpers ----------------
__device__ __forceinline__ float gelu_f(float x) {
    return 0.5f * x * (1.0f + erff(x * 0.70710678118654752440f));
}

// pack two f32 -> f16x2 (lo half = a, hi half = b)
__device__ __forceinline__ uint32_t cvt2h(float a, float b) {
    uint32_t r;
    asm("cvt.rn.f16x2.f32 %0, %1, %2;" : "=r"(r) : "f"(b), "f"(a));
    return r;
}

__device__ __forceinline__ void mma_f16(float c[4], const uint32_t a[4],
                                        uint32_t b0, uint32_t b1) {
    asm volatile("mma.sync.aligned.m16n8k16.row.col.f32.f16.f16.f32 "
                 "{%0,%1,%2,%3}, {%4,%5,%6,%7}, {%8,%9}, {%0,%1,%2,%3};"
                 : "+f"(c[0]), "+f"(c[1]), "+f"(c[2]), "+f"(c[3])
                 : "r"(a[0]), "r"(a[1]), "r"(a[2]), "r"(a[3]), "r"(b0), "r"(b1));
}

// Single-precision (1-pass) W fragment table, two nb packed per uint4:
//   sf[ks][np][lane] = {nb0.b0, nb0.b1, nb1.b0, nb1.b1},  nb0=2*np, nb1=2*np+1
template<int KDIM>
__device__ __forceinline__ void build_wtable(uint4* sf, const float* __restrict__ W,
                                             int tid, int nthreads) {
    constexpr int NKS = KDIM / 16;
    for (int idx = tid; idx < NKS * 8 * 32; idx += nthreads) {
        int li = idx & 31, np = (idx >> 5) & 7, ks = idx >> 8;
        int n0 = (2 * np) * 8 + (li >> 2);
        int n1 = n0 + 8;
        int kg = ks * 16 + (li & 3) * 2;
        uint4 f;
        f.x = cvt2h(W[(size_t)kg * HH + n0],       W[(size_t)(kg + 1) * HH + n0]);
        f.y = cvt2h(W[(size_t)(kg + 8) * HH + n0], W[(size_t)(kg + 9) * HH + n0]);
        f.z = cvt2h(W[(size_t)kg * HH + n1],       W[(size_t)(kg + 1) * HH + n1]);
        f.w = cvt2h(W[(size_t)(kg + 8) * HH + n1], W[(size_t)(kg + 9) * HH + n1]);
        sf[idx] = f;
    }
}

// ======================================================================
// Kernel 0: cs[g] = gelu(concat(emb_chg[charge], emb_spin[spin]) @ W_cs + b_cs)
// ======================================================================
__global__ void cs_kernel(const int* __restrict__ charge, const int* __restrict__ spin,
                          const float* __restrict__ emb_chg, const float* __restrict__ emb_spin,
                          const float* __restrict__ W_cs, const float* __restrict__ b_cs) {
    __shared__ float xv[2 * HH];
    int g = blockIdx.x, j = threadIdx.x;
    int c = charge[g], s = spin[g];
    xv[j]      = emb_chg[c * HH + j];
    xv[HH + j] = emb_spin[s * HH + j];
    __syncthreads();
    float acc = b_cs[j];
    #pragma unroll 8
    for (int k = 0; k < 2 * HH; k++) acc += xv[k] * W_cs[k * HH + j];
    g_cs[g * HH + j] = gelu_f(acc);
}

// ======================================================================
// Kernel 1: node features — embed/LN fp32, GEMM via fp16 HMMA 1-pass.
// Output -> g_nfrag (fp16 fragments).
// ======================================================================
#define SXS 264
#define SMEM_NODE (65536 + 16 * SXS * 4)

__global__ void __launch_bounds__(256, 1)
node_kernel(const int* __restrict__ an, const float* __restrict__ nde,
            const int* __restrict__ nbatch,
            const float* __restrict__ emb_atom, const float* __restrict__ W_nd,
            const float* __restrict__ b_nd, const float* __restrict__ ln_g,
            const float* __restrict__ ln_b, const float* __restrict__ W_node,
            const float* __restrict__ b_node) {
    extern __shared__ char dyn_smem[];
    uint4* sfW = (uint4*)dyn_smem;              // [16][8][32]
    float* sx  = (float*)(dyn_smem + 65536);    // [16][SXS]
    __shared__ float smu[16], srs[16];
    const int tid = threadIdx.x, lane = tid & 31, wid = tid >> 5;
    const int lr = lane >> 2, kc = (lane & 3) * 2;

    build_wtable<256>(sfW, W_node, tid, 256);
    __syncthreads();

    for (int t0 = blockIdx.x; t0 < NT_N; t0 += gridDim.x) {
        __syncthreads();   // sx reuse fence
        int n0 = t0 * 16;
        for (int idx = tid; idx < 16 * HH; idx += 256) {
            int n = idx >> 7, j = idx & 127;
            int node = n0 + n;
            float a = emb_atom[an[node] * HH + j];
            float accv = b_nd[j];
            const float* nrow = nde + node * NDD;
            #pragma unroll
            for (int k = 0; k < NDD; k++) accv += nrow[k] * W_nd[k * HH + j];
            sx[n * SXS + j]      = a;
            sx[n * SXS + HH + j] = gelu_f(accv);
        }
        __syncthreads();
        for (int n = wid; n < 16; n += 8) {
            float s1 = 0.f, s2 = 0.f;
            for (int k = lane; k < 256; k += 32) {
                float v = sx[n * SXS + k]; s1 += v; s2 += v * v;
            }
            #pragma unroll
            for (int o = 16; o > 0; o >>= 1) {
                s1 += __shfl_down_sync(0xffffffffu, s1, o);
                s2 += __shfl_down_sync(0xffffffffu, s2, o);
            }
            if (lane == 0) {
                float mu  = s1 * (1.f / 256.f);
                float var = s2 * (1.f / 256.f) - mu * mu;
                smu[n] = mu; srs[n] = rsqrtf(var + 1e-5f);
            }
        }
        __syncthreads();
        for (int idx = tid; idx < 16 * 256; idx += 256) {
            int n = idx >> 8, k = idx & 255;
            sx[n * SXS + k] =
                (sx[n * SXS + k] - smu[n]) * srs[n] * ln_g[k] + ln_b[k];
        }
        __syncthreads();
        // ---- GEMM [16,256]@[256,128]; warp handles nb = 2*wid, 2*wid+1 (np = wid)
        {
            float acc[2][4];
            #pragma unroll
            for (int i = 0; i < 2; i++) {
                float2 b = *(const float2*)(b_node + (wid * 2 + i) * 8 + kc);
                acc[i][0] = b.x; acc[i][1] = b.y; acc[i][2] = b.x; acc[i][3] = b.y;
            }
            #pragma unroll
            for (int ks = 0; ks < 16; ks++) {
                const float* x0 = sx + lr * SXS + ks * 16 + kc;
                const float* x1 = x0 + 8 * SXS;
                uint32_t ah[4];
                ah[0] = cvt2h(x0[0], x0[1]);
                ah[1] = cvt2h(x1[0], x1[1]);
                ah[2] = cvt2h(x0[8], x0[9]);
                ah[3] = cvt2h(x1[8], x1[9]);
                uint4 f = sfW[ks * 256 + wid * 32 + lane];
                mma_f16(acc[0], ah, f.x, f.y);
                mma_f16(acc[1], ah, f.z, f.w);
            }
            // epilogue: gelu + cs add, convert to fp16 fragment form.
            const int node0 = n0 + lr, node1 = node0 + 8;
            const float* cs0 = g_cs + nbatch[node0] * HH;
            const float* cs1 = g_cs + nbatch[node1] * HH;
            const int col0 = wid * 16 + kc;
            const int col1 = col0 + 8;
            uint32_t h0, h1;
            h0 = cvt2h(gelu_f(acc[0][0]) + cs0[col0], gelu_f(acc[0][1]) + cs0[col0 + 1]);
            h1 = cvt2h(gelu_f(acc[1][0]) + cs0[col1], gelu_f(acc[1][1]) + cs0[col1 + 1]);
            g_nfrag[(size_t)node0 * 32 + wid * 4 + (kc >> 1)] = make_uint2(h0, h1);
            h0 = cvt2h(gelu_f(acc[0][2]) + cs1[col0], gelu_f(acc[0][3]) + cs1[col0 + 1]);
            h1 = cvt2h(gelu_f(acc[1][2]) + cs1[col1], gelu_f(acc[1][3]) + cs1[col1 + 1]);
            g_nfrag[(size_t)node1 * 32 + wid * 4 + (kc >> 1)] = make_uint2(h0, h1);
        }
    }
}

// ======================================================================
// Edge kernel 1: eattr = gelu([edist|edir] @ W_edge + b_edge), K=192.
// 512 threads, 16 warps 8(m)x2(n), warp tile 32x64, tile = 256 edges.
// fp16 1-pass; per kstep: 8 LDG + 4 LDS.128 + 16 MMA.
// Output stored in fp16 fragment form.
// ======================================================================
__global__ void __launch_bounds__(512, 1)
edge1_hmma(const float* __restrict__ P0, const float* __restrict__ P1,
           const float* __restrict__ W, const float* __restrict__ bias)
{
    constexpr int NKS = 12;
    extern __shared__ char dyn_smem[];
    uint4* sf = (uint4*)dyn_smem;          // [12][8][32]

    const int tid = threadIdx.x, lane = tid & 31, wid = tid >> 5;
    const int warp_m = wid & 7, warp_n = wid >> 3;
    const int lr = lane >> 2, kc = (lane & 3) * 2, q = lane & 3;

    build_wtable<192>(sf, W, tid, 512);
    __syncthreads();

    // this warp's 4 nb-pairs start at np = warp_n*4
    const uint4* wfl = sf + (size_t)warp_n * 4 * 32 + lane;

    for (int tile = blockIdx.x; tile < NT_E; tile += gridDim.x) {
        const int e0 = tile * 256;
        const int mb0 = e0 + warp_m * 32 + lr;   // rows: mb0 + r*8, r=0..3
        const float* pA = P0 + (size_t)mb0 * EDD + kc;
        const float* pB = P1 + (size_t)mb0 * DD2D + kc;

        float acc[2][8][4];
        #pragma unroll
        for (int i = 0; i < 8; i++) {
            float2 b = *(const float2*)(bias + (warp_n * 8 + i) * 8 + kc);
            #pragma unroll
            for (int mf = 0; mf < 2; mf++) {
                acc[mf][i][0] = b.x; acc[mf][i][1] = b.y;
                acc[mf][i][2] = b.x; acc[mf][i][3] = b.y;
            }
        }

        float2 v[4][2];
        #define LOADA(KG)                                                          \
        {                                                                          \
            _Pragma("unroll")                                                      \
            for (int r = 0; r < 4; r++) {                                          \
                const float* qq = ((KG) < 128) ? pA + r * 8 * EDD + (KG)           \
                                               : pB + r * 8 * DD2D + ((KG) - 128); \
                v[r][0] = *(const float2*)qq;                                      \
                v[r][1] = *(const float2*)(qq + 8);                                \
            }                                                                      \
        }

        LOADA(0);

        #pragma unroll
        for (int ks = 0; ks < NKS; ks++) {
            uint32_t ah0[4], ah1[4];
            ah0[0] = cvt2h(v[0][0].x, v[0][0].y);
            ah0[1] = cvt2h(v[1][0].x, v[1][0].y);
            ah0[2] = cvt2h(v[0][1].x, v[0][1].y);
            ah0[3] = cvt2h(v[1][1].x, v[1][1].y);
            ah1[0] = cvt2h(v[2][0].x, v[2][0].y);
            ah1[1] = cvt2h(v[3][0].x, v[3][0].y);
            ah1[2] = cvt2h(v[2][1].x, v[2][1].y);
            ah1[3] = cvt2h(v[3][1].x, v[3][1].y);
            if (ks + 1 < NKS) LOADA((ks + 1) * 16);

            const uint4* wk = wfl + ks * 256;
            #pragma unroll
            for (int j = 0; j < 4; j++) {
                uint4 f = wk[j * 32];
                mma_f16(acc[0][2 * j + 0], ah0, f.x, f.y);
                mma_f16(acc[0][2 * j + 1], ah0, f.z, f.w);
                mma_f16(acc[1][2 * j + 0], ah1, f.x, f.y);
                mma_f16(acc[1][2 * j + 1], ah1, f.z, f.w);
            }
        }
        #undef LOADA

        // ---- epilogue: gelu, convert to fp16 fragments.
        // nb pair (i0=2j, i1=2j+1) -> ksIdx = warp_n*4 + j.
        #pragma unroll
        for (int mf = 0; mf < 2; mf++) {
            const size_t ra = (size_t)(mb0 + mf * 16);
            #pragma unroll
            for (int j = 0; j < 4; j++) {
                const int i0 = 2 * j, i1 = 2 * j + 1;
                const int ksIdx = warp_n * 4 + j;
                uint32_t h0, h1;
                h0 = cvt2h(gelu_f(acc[mf][i0][0]), gelu_f(acc[mf][i0][1]));
                h1 = cvt2h(gelu_f(acc[mf][i1][0]), gelu_f(acc[mf][i1][1]));
                g_efrag[ra * 32 + ksIdx * 4 + q] = make_uint2(h0, h1);
                h0 = cvt2h(gelu_f(acc[mf][i0][2]), gelu_f(acc[mf][i0][3]));
                h1 = cvt2h(gelu_f(acc[mf][i1][2]), gelu_f(acc[mf][i1][3]));
                g_efrag[(ra + 8) * 32 + ksIdx * 4 + q] = make_uint2(h0, h1);
            }
        }
    }
}

// ======================================================================
// Edge kernel 2: out = gelu([node[src]|eattr] @ W_ef + b_ef), K=256.
// A comes PRE-CONVERTED fp16 fragments (g_nfrag ks<8, g_efrag ks>=8):
// per k-step 4x LDG.64 + 4x LDS.128 + 16 MMA, fp16 1-pass.
// ======================================================================
__global__ void __launch_bounds__(512, 1)
edge2_hmma(const int* __restrict__ srcIdx, const float* __restrict__ W,
           const float* __restrict__ bias, float* __restrict__ outp)
{
    extern __shared__ char dyn_smem[];
    uint4* sf = (uint4*)dyn_smem;          // [16][8][32]

    const int tid = threadIdx.x, lane = tid & 31, wid = tid >> 5;
    const int warp_m = wid & 7, warp_n = wid >> 3;
    const int lr = lane >> 2, kc = (lane & 3) * 2, q = lane & 3;

    build_wtable<256>(sf, W, tid, 512);
    __syncthreads();

    const uint4* wfl = sf + (size_t)warp_n * 4 * 32 + lane;

    for (int tile = blockIdx.x; tile < NT_E; tile += gridDim.x) {
        const int e0 = tile * 256;
        const int mb0 = e0 + warp_m * 32 + lr;   // rows: mb0 + r*8, r=0..3

        uint32_t offN[4];
        #pragma unroll
        for (int r = 0; r < 4; r++)
            offN[r] = (uint32_t)srcIdx[mb0 + r * 8] * 32;
        const uint2* nbase = g_nfrag + q;
        const uint2* ebase = g_efrag + (size_t)mb0 * 32 + q;

        float acc[2][8][4];
        #pragma unroll
        for (int i = 0; i < 8; i++) {
            float2 b = *(const float2*)(bias + (warp_n * 8 + i) * 8 + kc);
            #pragma unroll
            for (int mf = 0; mf < 2; mf++) {
                acc[mf][i][0] = b.x; acc[mf][i][1] = b.y;
                acc[mf][i][2] = b.x; acc[mf][i][3] = b.y;
            }
        }

        uint2 va[4], vb[4];
        #define LOADA(KS, BUF)                                                        \
        {                                                                             \
            if ((KS) < 8) {                                                           \
                _Pragma("unroll")                                                     \
                for (int r = 0; r < 4; r++) BUF[r] = nbase[offN[r] + (KS) * 4];       \
            } else {                                                                  \
                _Pragma("unroll")                                                     \
                for (int r = 0; r < 4; r++) BUF[r] = ebase[r * 256 + ((KS) - 8) * 4]; \
            }                                                                         \
        }

        LOADA(0, va);

        #pragma unroll
        for (int ks = 0; ks < 16; ks++) {
            uint2* cur = (ks & 1) ? vb : va;
            uint2* nxt = (ks & 1) ? va : vb;
            if (ks + 1 < 16) LOADA(ks + 1, nxt);

            // a-operands by register selection — zero instructions
            uint32_t ah0[4] = {cur[0].x, cur[1].x, cur[0].y, cur[1].y};
            uint32_t ah1[4] = {cur[2].x, cur[3].x, cur[2].y, cur[3].y};

            const uint4* wk = wfl + ks * 256;
            #pragma unroll
            for (int j = 0; j < 4; j++) {
                uint4 f = wk[j * 32];
                mma_f16(acc[0][2 * j + 0], ah0, f.x, f.y);
                mma_f16(acc[0][2 * j + 1], ah0, f.z, f.w);
                mma_f16(acc[1][2 * j + 0], ah1, f.x, f.y);
                mma_f16(acc[1][2 * j + 1], ah1, f.z, f.w);
            }
        }
        #undef LOADA

        // ---- epilogue: gelu + fp32 store to output ----
        #pragma unroll
        for (int mf = 0; mf < 2; mf++) {
            const int ra = mb0 + mf * 16;
            #pragma unroll
            for (int i = 0; i < 8; i++) {
                const int col = (warp_n * 8 + i) * 8 + kc;
                float2 o0, o1;
                o0.x = gelu_f(acc[mf][i][0]); o0.y = gelu_f(acc[mf][i][1]);
                o1.x = gelu_f(acc[mf][i][2]); o1.y = gelu_f(acc[mf][i][3]);
                *(float2*)(outp + (size_t)ra * HH + col)       = o0;
                *(float2*)(outp + (size_t)(ra + 8) * HH + col) = o1;
            }
        }
    }
}

#define SMEM_E1 (12 * 8 * 32 * 16)   // 49,152 B
#define SMEM_E2 (16 * 8 * 32 * 16)   // 65,536 B

// ======================================================================
// launch
// ======================================================================
extern "C" void kernel_launch(void* const* d_in, const int* in_sizes, int n_in,
                              void* d_out, int out_size) {
    const int*   atomic_numbers = (const int*)  d_in[0];
    const float* nde            = (const float*)d_in[1];
    const float* edist          = (const float*)d_in[2];
    const float* edir           = (const float*)d_in[3];
    const int*   charge         = (const int*)  d_in[4];
    const int*   spin           = (const int*)  d_in[5];
    const int*   nbatch         = (const int*)  d_in[6];
    const int*   nsrc           = (const int*)  d_in[7];
    const float* emb_atom       = (const float*)d_in[8];
    const float* W_nd           = (const float*)d_in[9];
    const float* b_nd           = (const float*)d_in[10];
    const float* ln_g           = (const float*)d_in[11];
    const float* ln_b           = (const float*)d_in[12];
    const float* W_node         = (const float*)d_in[13];
    const float* b_node         = (const float*)d_in[14];
    const float* emb_chg        = (const float*)d_in[15];
    const float* emb_spin       = (const float*)d_in[16];
    const float* W_cs           = (const float*)d_in[17];
    const float* b_cs           = (const float*)d_in[18];
    const float* W_edge         = (const float*)d_in[19];
    const float* b_edge         = (const float*)d_in[20];
    const float* W_ef           = (const float*)d_in[21];
    const float* b_ef           = (const float*)d_in[22];
    float* out = (float*)d_out;

    cudaFuncSetAttribute(node_kernel, cudaFuncAttributeMaxDynamicSharedMemorySize, SMEM_NODE);
    cudaFuncSetAttribute(edge1_hmma,  cudaFuncAttributeMaxDynamicSharedMemorySize, SMEM_E1);
    cudaFuncSetAttribute(edge2_hmma,  cudaFuncAttributeMaxDynamicSharedMemorySize, SMEM_E2);

    int nsm = 148;
    cudaDeviceGetAttribute(&nsm, cudaDevAttrMultiProcessorCount, 0);

    cs_kernel<<<NG, HH>>>(charge, spin, emb_chg, emb_spin, W_cs, b_cs);
    node_kernel<<<nsm, 256, SMEM_NODE>>>(atomic_numbers, nde, nbatch, emb_atom,
                                         W_nd, b_nd, ln_g, ln_b, W_node, b_node);
    edge1_hmma<<<nsm, 512, SMEM_E1>>>(edist, edir, W_edge, b_edge);
    edge2_hmma<<<nsm, 512, SMEM_E2>>>(nsrc, W_ef, b_ef, out);
}